// round 1
// baseline (speedup 1.0000x reference)
#include <cuda_runtime.h>

#define N_NODES 8192
#define F_IN    512
#define F_OUT   64
#define NEG_BIG (-9e15f)
#define TI 32     // rows per attention block
#define TJ 128    // j tile

// Scratch (device globals; no allocation allowed)
__device__ float g_Wh[N_NODES * F_OUT];
__device__ float g_s1[N_NODES];
__device__ float g_s2[N_NODES];

// ---- packed f32x2 helpers (Blackwell FFMA2 only reachable via PTX) ----
__device__ __forceinline__ unsigned long long pack2(float x, float y) {
    unsigned long long r;
    asm("mov.b64 %0, {%1, %2};" : "=l"(r) : "f"(x), "f"(y));
    return r;
}
__device__ __forceinline__ void unpack2(unsigned long long v, float& x, float& y) {
    asm("mov.b64 {%0, %1}, %2;" : "=f"(x), "=f"(y) : "l"(v));
}
__device__ __forceinline__ unsigned long long fma2(unsigned long long a, unsigned long long b, unsigned long long c) {
    unsigned long long d;
    asm("fma.rn.f32x2 %0, %1, %2, %3;" : "=l"(d) : "l"(a), "l"(b), "l"(c));
    return d;
}
__device__ __forceinline__ unsigned long long mul2(unsigned long long a, unsigned long long b) {
    unsigned long long d;
    asm("mul.rn.f32x2 %0, %1, %2;" : "=l"(d) : "l"(a), "l"(b));
    return d;
}

// ---------------------------------------------------------------------------
// Kernel 1: Wh = h @ W   (8192x512 @ 512x64)
// Block: 256 threads handles 64 rows. Thread (c = t&63, rq = t>>6) computes 16 rows.
// ---------------------------------------------------------------------------
__global__ __launch_bounds__(256) void gat_gemm(const float* __restrict__ h,
                                                const float* __restrict__ W) {
    __shared__ float hs[64][32];
    __shared__ float Ws[32][64];
    int t = threadIdx.x;
    int c = t & 63;
    int rq = t >> 6;                 // 0..3
    int row0 = blockIdx.x * 64;

    float acc[16];
#pragma unroll
    for (int i = 0; i < 16; i++) acc[i] = 0.f;

    for (int kt = 0; kt < F_IN; kt += 32) {
        __syncthreads();
#pragma unroll
        for (int i = 0; i < 8; i++) {            // 64x32 h tile
            int lin = t + i * 256;
            int r = lin >> 5, k = lin & 31;
            hs[r][k] = h[(size_t)(row0 + r) * F_IN + kt + k];
        }
#pragma unroll
        for (int i = 0; i < 8; i++) {            // 32x64 W tile
            int lin = t + i * 256;
            int k = lin >> 6, cc = lin & 63;
            Ws[k][cc] = W[(kt + k) * F_OUT + cc];
        }
        __syncthreads();
#pragma unroll
        for (int kk = 0; kk < 32; kk++) {
            float w = Ws[kk][c];
#pragma unroll
            for (int rr = 0; rr < 16; rr++)
                acc[rr] += hs[rq * 16 + rr][kk] * w;
        }
    }
#pragma unroll
    for (int rr = 0; rr < 16; rr++)
        g_Wh[(size_t)(row0 + rq * 16 + rr) * F_OUT + c] = acc[rr];
}

// ---------------------------------------------------------------------------
// Kernel 2: s1[i] = Wh[i,:] . a[0:64],  s2[i] = Wh[i,:] . a[64:128]
// One warp per row.
// ---------------------------------------------------------------------------
__global__ __launch_bounds__(256) void gat_s(const float* __restrict__ a) {
    int warp = (blockIdx.x * blockDim.x + threadIdx.x) >> 5;
    int lane = threadIdx.x & 31;
    if (warp >= N_NODES) return;
    float w0 = g_Wh[(size_t)warp * F_OUT + lane];
    float w1 = g_Wh[(size_t)warp * F_OUT + 32 + lane];
    float p1 = w0 * a[lane] + w1 * a[lane + 32];
    float p2 = w0 * a[64 + lane] + w1 * a[96 + lane];
#pragma unroll
    for (int m = 16; m > 0; m >>= 1) {
        p1 += __shfl_xor_sync(0xffffffffu, p1, m);
        p2 += __shfl_xor_sync(0xffffffffu, p2, m);
    }
    if (lane == 0) { g_s1[warp] = p1; g_s2[warp] = p2; }
}

// ---------------------------------------------------------------------------
// Kernel 3: fused masked softmax + P@Wh + elu.
// Block = 256 threads = 32 groups x 8 lanes; group g owns row i.
// Lane l processes j = l (mod 8) with a private online softmax, merged at end.
// Wh staged in smem with 68-float row stride -> conflict-free LDS.128
// (bank offset 4*(j+c) mod 32 distinct across the 8 lanes of a group).
// ---------------------------------------------------------------------------
__global__ __launch_bounds__(256) void gat_attn(const int* __restrict__ adj,
                                                float* __restrict__ out) {
    __shared__ float whs[TJ][68];
    int t = threadIdx.x;
    int lane8 = t & 7;
    int g = t >> 3;                        // 0..31
    int i = blockIdx.x * TI + g;

    float s1i = g_s1[i];
    float m = -__int_as_float(0x7f800000) * 1.0f;  // -inf
    m = -INFINITY;
    float l = 0.f;
    unsigned long long acc[32];
#pragma unroll
    for (int q = 0; q < 32; q++) acc[q] = 0ULL;    // (0.f, 0.f)

    const int* adjrow = adj + (size_t)i * N_NODES;

    for (int j0 = 0; j0 < N_NODES; j0 += TJ) {
        __syncthreads();
#pragma unroll
        for (int q = 0; q < 8; q++) {              // 128x64 Wh tile, float4 coalesced
            int lin = t + q * 256;                 // 0..2047
            int r = lin >> 4;                      // 0..127
            int c4 = (lin & 15) << 2;              // 0,4,...,60
            float4 v = *(const float4*)(g_Wh + (size_t)(j0 + r) * F_OUT + c4);
            *(float4*)(&whs[r][c4]) = v;
        }
        __syncthreads();

#pragma unroll 1
        for (int jj = lane8; jj < TJ; jj += 8) {
            int aij = adjrow[j0 + jj];
            float z = s1i + g_s2[j0 + jj];
            float e = (z > 0.f) ? z : 0.2f * z;    // leaky_relu(0.2)
            e = (aij > 0) ? e : NEG_BIG;           // mask
            if (e > m) {                           // rare after warmup
                float sc = __expf(m - e);
                l *= sc;
                unsigned long long sc2 = pack2(sc, sc);
#pragma unroll
                for (int q = 0; q < 32; q++) acc[q] = mul2(acc[q], sc2);
                m = e;
            }
            float p = __expf(e - m);               // ==0 exactly for masked j
            l += p;
            unsigned long long p2 = pack2(p, p);
            const ulonglong2* wp = (const ulonglong2*)(&whs[jj][0]);
#pragma unroll
            for (int q = 0; q < 16; q++) {
                ulonglong2 w2 = wp[q];
                acc[2 * q]     = fma2(p2, w2.x, acc[2 * q]);
                acc[2 * q + 1] = fma2(p2, w2.y, acc[2 * q + 1]);
            }
        }
    }

    // ---- merge the 8 per-lane partial softmaxes of this row ----
    float M = m;
#pragma unroll
    for (int d = 1; d < 8; d <<= 1) M = fmaxf(M, __shfl_xor_sync(0xffffffffu, M, d));
    float w = __expf(m - M);
    float lw = l * w;
#pragma unroll
    for (int d = 1; d < 8; d <<= 1) lw += __shfl_xor_sync(0xffffffffu, lw, d);
    float invl = 1.f / lw;

#pragma unroll
    for (int q = 0; q < 32; q++) {
        float lo, hi;
        unpack2(acc[q], lo, hi);
        lo *= w; hi *= w;
#pragma unroll
        for (int d = 1; d < 8; d <<= 1) {
            lo += __shfl_xor_sync(0xffffffffu, lo, d);
            hi += __shfl_xor_sync(0xffffffffu, hi, d);
        }
        if ((q & 7) == lane8) {
            float v0 = lo * invl;
            float v1 = hi * invl;
            v0 = (v0 > 0.f) ? v0 : expm1f(v0);     // elu, alpha=1
            v1 = (v1 > 0.f) ? v1 : expm1f(v1);
            *(float2*)(out + (size_t)i * F_OUT + 2 * q) = make_float2(v0, v1);
        }
    }
}

// ---------------------------------------------------------------------------
extern "C" void kernel_launch(void* const* d_in, const int* in_sizes, int n_in,
                              void* d_out, int out_size) {
    const float* h   = (const float*)d_in[0];
    const float* W   = (const float*)d_in[1];
    const float* a   = (const float*)d_in[2];
    const int*   adj = (const int*)d_in[3];
    float* out = (float*)d_out;

    gat_gemm<<<N_NODES / 64, 256>>>(h, W);
    gat_s<<<N_NODES / 8, 256>>>(a);
    gat_attn<<<N_NODES / TI, 256>>>(adj, out);
}

// round 2
// speedup vs baseline: 2.2572x; 2.2572x over previous
#include <cuda_runtime.h>

#define N_NODES 8192
#define F_IN    512
#define F_OUT   64
#define ALPHA   0.2f
#define BM      64
#define TJ      32
#define SPLITS  4
#define KS      (N_NODES / SPLITS)   // 2048

__device__ __align__(16) float g_Wh[N_NODES * F_OUT];
__device__ __align__(16) float g_s1[N_NODES];
__device__ __align__(16) float g_s2[N_NODES];
__device__ float g_M2;
__device__ __align__(16) float g_pacc[SPLITS][N_NODES][F_OUT];
__device__ __align__(16) float g_pl[SPLITS][N_NODES];

// ---- packed f32x2 helpers (FFMA2 only reachable via PTX) ----
__device__ __forceinline__ unsigned long long pack2(float x, float y) {
    unsigned long long r;
    asm("mov.b64 %0, {%1, %2};" : "=l"(r) : "f"(x), "f"(y));
    return r;
}
__device__ __forceinline__ void unpack2(unsigned long long v, float& x, float& y) {
    asm("mov.b64 {%0, %1}, %2;" : "=f"(x), "=f"(y) : "l"(v));
}
__device__ __forceinline__ unsigned long long fma2(unsigned long long a, unsigned long long b, unsigned long long c) {
    unsigned long long d;
    asm("fma.rn.f32x2 %0, %1, %2, %3;" : "=l"(d) : "l"(a), "l"(b), "l"(c));
    return d;
}

// ---------------------------------------------------------------------------
// Kernel 1: Wh = h @ W   (8192x512 @ 512x64). 256 blocks x 32 rows.
// ---------------------------------------------------------------------------
__global__ __launch_bounds__(256) void gat_gemm(const float* __restrict__ h,
                                                const float* __restrict__ W) {
    __shared__ float hs[32][36];
    __shared__ float Ws[32][64];
    int t = threadIdx.x;
    int c = t & 63;
    int rg = t >> 6;                 // 0..3 -> rows rg*8..rg*8+7
    int row0 = blockIdx.x * 32;

    float acc[8];
#pragma unroll
    for (int r = 0; r < 8; r++) acc[r] = 0.f;

    for (int kt = 0; kt < F_IN; kt += 32) {
        __syncthreads();
        {   // 32x32 h tile, one float4 per thread
            int r = t >> 3, k4 = (t & 7) << 2;
            float4 v = *(const float4*)(h + (size_t)(row0 + r) * F_IN + kt + k4);
            *(float4*)&hs[r][k4] = v;
        }
#pragma unroll
        for (int q = 0; q < 2; q++) {   // 32x64 W tile
            int lin = t + q * 256;
            int kk = lin >> 4, c4 = (lin & 15) << 2;
            *(float4*)&Ws[kk][c4] = *(const float4*)(W + (size_t)(kt + kk) * F_OUT + c4);
        }
        __syncthreads();
#pragma unroll
        for (int kk = 0; kk < 32; kk++) {
            float w = Ws[kk][c];
#pragma unroll
            for (int r = 0; r < 8; r++)
                acc[r] += hs[rg * 8 + r][kk] * w;
        }
    }
#pragma unroll
    for (int r = 0; r < 8; r++)
        g_Wh[(size_t)(row0 + rg * 8 + r) * F_OUT + c] = acc[r];
}

// ---------------------------------------------------------------------------
// Kernel 2: s1[i] = Wh[i,:].a1, s2[i] = Wh[i,:].a2. One warp per row.
// ---------------------------------------------------------------------------
__global__ __launch_bounds__(256) void gat_s(const float* __restrict__ a) {
    int warp = (blockIdx.x * blockDim.x + threadIdx.x) >> 5;
    int lane = threadIdx.x & 31;
    float w0 = g_Wh[(size_t)warp * F_OUT + lane];
    float w1 = g_Wh[(size_t)warp * F_OUT + 32 + lane];
    float p1 = w0 * a[lane] + w1 * a[lane + 32];
    float p2 = w0 * a[64 + lane] + w1 * a[96 + lane];
#pragma unroll
    for (int m = 16; m > 0; m >>= 1) {
        p1 += __shfl_xor_sync(0xffffffffu, p1, m);
        p2 += __shfl_xor_sync(0xffffffffu, p2, m);
    }
    if (lane == 0) { g_s1[warp] = p1; g_s2[warp] = p2; }
}

// ---------------------------------------------------------------------------
// Kernel 2b: M2 = max_j s2[j]  (global max -> valid softmax shift, monotone lrelu)
// ---------------------------------------------------------------------------
__global__ void gat_max() {
    __shared__ float red[256];
    int t = threadIdx.x;
    float m = -1e30f;
    for (int i = t; i < N_NODES; i += 256) m = fmaxf(m, g_s2[i]);
    red[t] = m;
    __syncthreads();
#pragma unroll
    for (int s = 128; s > 0; s >>= 1) {
        if (t < s) red[t] = fmaxf(red[t], red[t + s]);
        __syncthreads();
    }
    if (t == 0) g_M2 = red[0];
}

// ---------------------------------------------------------------------------
// Kernel 3: split-K masked-softmax GEMM.
// Block = 64 i x 64 c output tile, one K-split of 2048 j.
// Per tile: phase1 computes P[32j][64i] in smem (+ row sums), phase2 does
// register-tiled (4i x 4c per thread) P @ Whs with packed FFMA2.
// ---------------------------------------------------------------------------
__global__ __launch_bounds__(256, 4) void gat_attn(const int* __restrict__ adj) {
    __shared__ float Ps[TJ][BM + 4];     // stride 68 floats (272B, 16B-aligned rows)
    __shared__ float Whs[TJ][F_OUT];
    __shared__ float sm_s1[BM], sm_m[BM], sl[BM];

    int t = threadIdx.x;
    int i0 = blockIdx.x * BM;
    int sp = blockIdx.y;
    int j0base = sp * KS;
    int cg = t & 15;                     // cols 4*cg .. +3
    int ig = t >> 4;                     // rows 4*ig .. +3

    if (t < BM) {
        float s1 = g_s1[i0 + t];
        float z = s1 + g_M2;
        sm_s1[t] = s1;
        sm_m[t] = z > 0.f ? z : ALPHA * z;   // upper bound of row's e (monotone lrelu)
        sl[t] = 0.f;
    }

    unsigned long long acc[4][2];
#pragma unroll
    for (int r = 0; r < 4; r++) { acc[r][0] = 0ULL; acc[r][1] = 0ULL; }

    for (int jt = 0; jt < KS; jt += TJ) {
        int j0 = j0base + jt;
        __syncthreads();                 // prev phase2 reads done

        // stage Whs (32x64 floats)
#pragma unroll
        for (int q = 0; q < 2; q++) {
            int lin = t + q * 256;
            int r = lin >> 4, c4 = (lin & 15) << 2;
            *(float4*)&Whs[r][c4] = *(const float4*)(g_Wh + (size_t)(j0 + r) * F_OUT + c4);
        }

        // phase 1: P tile + row-sum contributions
#pragma unroll
        for (int pass = 0; pass < 2; pass++) {
            int iloc = pass * 32 + (t >> 3);
            int jb = (t & 7) << 2;
            float s1 = sm_s1[iloc], m = sm_m[iloc];
            int4 av = *(const int4*)(adj + (size_t)(i0 + iloc) * N_NODES + j0 + jb);
            float4 s2v = *(const float4*)(g_s2 + j0 + jb);

            float z0 = s1 + s2v.x, z1 = s1 + s2v.y, z2 = s1 + s2v.z, z3 = s1 + s2v.w;
            float e0 = z0 > 0.f ? z0 : ALPHA * z0;
            float e1 = z1 > 0.f ? z1 : ALPHA * z1;
            float e2 = z2 > 0.f ? z2 : ALPHA * z2;
            float e3 = z3 > 0.f ? z3 : ALPHA * z3;
            float p0 = (av.x > 0) ? __expf(e0 - m) : 0.f;
            float p1 = (av.y > 0) ? __expf(e1 - m) : 0.f;
            float p2 = (av.z > 0) ? __expf(e2 - m) : 0.f;
            float p3 = (av.w > 0) ? __expf(e3 - m) : 0.f;

            Ps[jb + 0][iloc] = p0;
            Ps[jb + 1][iloc] = p1;
            Ps[jb + 2][iloc] = p2;
            Ps[jb + 3][iloc] = p3;

            float ps = (p0 + p1) + (p2 + p3);
            ps += __shfl_down_sync(0xffffffffu, ps, 4, 8);
            ps += __shfl_down_sync(0xffffffffu, ps, 2, 8);
            ps += __shfl_down_sync(0xffffffffu, ps, 1, 8);
            if ((t & 7) == 0) sl[iloc] += ps;
        }
        __syncthreads();

        // phase 2: acc += P^T-frag @ Whs-frag  (4i x 4c per thread)
#pragma unroll 8
        for (int jj = 0; jj < TJ; jj++) {
            float4 pv = *(const float4*)&Ps[jj][ig << 2];
            float4 wv = *(const float4*)&Whs[jj][cg << 2];
            unsigned long long w01 = pack2(wv.x, wv.y);
            unsigned long long w23 = pack2(wv.z, wv.w);
            unsigned long long pp;
            pp = pack2(pv.x, pv.x);
            acc[0][0] = fma2(pp, w01, acc[0][0]);
            acc[0][1] = fma2(pp, w23, acc[0][1]);
            pp = pack2(pv.y, pv.y);
            acc[1][0] = fma2(pp, w01, acc[1][0]);
            acc[1][1] = fma2(pp, w23, acc[1][1]);
            pp = pack2(pv.z, pv.z);
            acc[2][0] = fma2(pp, w01, acc[2][0]);
            acc[2][1] = fma2(pp, w23, acc[2][1]);
            pp = pack2(pv.w, pv.w);
            acc[3][0] = fma2(pp, w01, acc[3][0]);
            acc[3][1] = fma2(pp, w23, acc[3][1]);
        }
    }
    __syncthreads();

#pragma unroll
    for (int r = 0; r < 4; r++) {
        int i = i0 + (ig << 2) + r;
        float x0, x1, x2, x3;
        unpack2(acc[r][0], x0, x1);
        unpack2(acc[r][1], x2, x3);
        *(float4*)&g_pacc[sp][i][cg << 2] = make_float4(x0, x1, x2, x3);
    }
    if (t < BM) g_pl[sp][i0 + t] = sl[t];
}

// ---------------------------------------------------------------------------
// Kernel 4: merge splits, normalize, elu.
// ---------------------------------------------------------------------------
__global__ __launch_bounds__(256) void gat_merge(float* __restrict__ out) {
    int idx = blockIdx.x * 256 + threadIdx.x;
    int i = idx >> 6;
    int c = idx & 63;
    float v = 0.f, l = 0.f;
#pragma unroll
    for (int s = 0; s < SPLITS; s++) {
        v += g_pacc[s][i][c];
        l += g_pl[s][i];
    }
    float r = v / l;
    out[idx] = r > 0.f ? r : expm1f(r);
}

// ---------------------------------------------------------------------------
extern "C" void kernel_launch(void* const* d_in, const int* in_sizes, int n_in,
                              void* d_out, int out_size) {
    const float* h   = (const float*)d_in[0];
    const float* W   = (const float*)d_in[1];
    const float* a   = (const float*)d_in[2];
    const int*   adj = (const int*)d_in[3];
    float* out = (float*)d_out;

    gat_gemm<<<N_NODES / 32, 256>>>(h, W);
    gat_s<<<N_NODES / 8, 256>>>(a);
    gat_max<<<1, 256>>>();
    gat_attn<<<dim3(N_NODES / BM, SPLITS), 256>>>(adj);
    gat_merge<<<N_NODES * F_OUT / 256, 256>>>(out);
}

// round 6
// speedup vs baseline: 4.1305x; 1.8299x over previous
#include <cuda_runtime.h>
#include <cuda_fp16.h>
#include <cstdint>

#define N_NODES 8192
#define F_IN    512
#define F_OUT   64
#define ALPHA   0.2f
#define BM      128                  // i rows per attn block
#define KC      64                   // j per chunk
#define SPLITS  4
#define KS      (N_NODES / SPLITS)   // 2048
#define NCHUNK  (KS / KC)            // 32

__device__ __align__(16) float  g_Wh[N_NODES * F_OUT];
__device__ __align__(16) __half g_Whh[N_NODES * F_OUT];   // row-major fp16
__device__ __align__(16) float  g_s1[N_NODES];
__device__ __align__(16) float  g_s2[N_NODES];
__device__ float g_M2;
__device__ __align__(16) float g_pacc[SPLITS][N_NODES][F_OUT];
__device__ __align__(16) float g_pl[SPLITS][N_NODES];

// ---------------- helpers ----------------
__device__ __forceinline__ uint32_t smem_u32(const void* p) {
    uint32_t a;
    asm("{ .reg .u64 t; cvta.to.shared.u64 t, %1; cvt.u32.u64 %0, t; }" : "=r"(a) : "l"(p));
    return a;
}
__device__ __forceinline__ uint32_t cvt_f16x2(float lo, float hi) {
    uint32_t r;
    asm("cvt.rn.f16x2.f32 %0, %1, %2;" : "=r"(r) : "f"(hi), "f"(lo));
    return r;
}
__device__ __forceinline__ void ldsm_x4(uint32_t& r0, uint32_t& r1, uint32_t& r2, uint32_t& r3, uint32_t addr) {
    asm volatile("ldmatrix.sync.aligned.m8n8.x4.shared.b16 {%0,%1,%2,%3}, [%4];"
                 : "=r"(r0), "=r"(r1), "=r"(r2), "=r"(r3) : "r"(addr));
}
__device__ __forceinline__ void ldsm_x4_t(uint32_t& r0, uint32_t& r1, uint32_t& r2, uint32_t& r3, uint32_t addr) {
    asm volatile("ldmatrix.sync.aligned.m8n8.x4.trans.shared.b16 {%0,%1,%2,%3}, [%4];"
                 : "=r"(r0), "=r"(r1), "=r"(r2), "=r"(r3) : "r"(addr));
}
__device__ __forceinline__ void mma_f16(float* c, uint32_t a0, uint32_t a1, uint32_t a2, uint32_t a3,
                                        uint32_t b0, uint32_t b1) {
    asm volatile(
        "mma.sync.aligned.m16n8k16.row.col.f32.f16.f16.f32 "
        "{%0,%1,%2,%3}, {%4,%5,%6,%7}, {%8,%9}, {%0,%1,%2,%3};"
        : "+f"(c[0]), "+f"(c[1]), "+f"(c[2]), "+f"(c[3])
        : "r"(a0), "r"(a1), "r"(a2), "r"(a3), "r"(b0), "r"(b1));
}

// ---------------------------------------------------------------------------
// Kernel 1: Wh = h @ W (fp32) + fp16 copy. Register-prefetch double buffer.
// ---------------------------------------------------------------------------
__global__ __launch_bounds__(256) void gat_gemm(const float* __restrict__ h,
                                                const float* __restrict__ W) {
    __shared__ float hs[32][36];
    __shared__ float Ws[32][64];
    int t = threadIdx.x;
    int c = t & 63;
    int rg = t >> 6;
    int row0 = blockIdx.x * 32;

    int hr = t >> 3, hk4 = (t & 7) << 2;
    int wk = t >> 4, wc4 = (t & 15) << 2;

    float acc[8];
#pragma unroll
    for (int r = 0; r < 8; r++) acc[r] = 0.f;

    float4 hreg = *(const float4*)(h + (size_t)(row0 + hr) * F_IN + hk4);
    float4 wreg0 = *(const float4*)(W + (size_t)wk * F_OUT + wc4);
    float4 wreg1 = *(const float4*)(W + (size_t)(wk + 16) * F_OUT + wc4);

    for (int kt = 0; kt < F_IN; kt += 32) {
        *(float4*)&hs[hr][hk4] = hreg;
        *(float4*)&Ws[wk][wc4] = wreg0;
        *(float4*)&Ws[wk + 16][wc4] = wreg1;
        __syncthreads();
        if (kt + 32 < F_IN) {
            hreg = *(const float4*)(h + (size_t)(row0 + hr) * F_IN + kt + 32 + hk4);
            wreg0 = *(const float4*)(W + (size_t)(kt + 32 + wk) * F_OUT + wc4);
            wreg1 = *(const float4*)(W + (size_t)(kt + 32 + wk + 16) * F_OUT + wc4);
        }
#pragma unroll
        for (int kk = 0; kk < 32; kk++) {
            float w = Ws[kk][c];
#pragma unroll
            for (int r = 0; r < 8; r++)
                acc[r] += hs[rg * 8 + r][kk] * w;
        }
        __syncthreads();
    }
#pragma unroll
    for (int r = 0; r < 8; r++) {
        int row = row0 + rg * 8 + r;
        g_Wh[(size_t)row * F_OUT + c] = acc[r];
        g_Whh[(size_t)row * F_OUT + c] = __float2half_rn(acc[r]);
    }
}

// ---------------------------------------------------------------------------
// Kernel 2: s1, s2 (one warp per row)
// ---------------------------------------------------------------------------
__global__ __launch_bounds__(256) void gat_s(const float* __restrict__ a) {
    int warp = (blockIdx.x * blockDim.x + threadIdx.x) >> 5;
    int lane = threadIdx.x & 31;
    float w0 = g_Wh[(size_t)warp * F_OUT + lane];
    float w1 = g_Wh[(size_t)warp * F_OUT + 32 + lane];
    float p1 = w0 * a[lane] + w1 * a[lane + 32];
    float p2 = w0 * a[64 + lane] + w1 * a[96 + lane];
#pragma unroll
    for (int m = 16; m > 0; m >>= 1) {
        p1 += __shfl_xor_sync(0xffffffffu, p1, m);
        p2 += __shfl_xor_sync(0xffffffffu, p2, m);
    }
    if (lane == 0) { g_s1[warp] = p1; g_s2[warp] = p2; }
}

__global__ void gat_max() {
    __shared__ float red[256];
    int t = threadIdx.x;
    float m = -1e30f;
    for (int i = t; i < N_NODES; i += 256) m = fmaxf(m, g_s2[i]);
    red[t] = m;
    __syncthreads();
#pragma unroll
    for (int s = 128; s > 0; s >>= 1) {
        if (t < s) red[t] = fmaxf(red[t], red[t + s]);
        __syncthreads();
    }
    if (t == 0) g_M2 = red[0];
}

// ---------------------------------------------------------------------------
// Kernel 3: masked-softmax GEMM via mma.sync fp16 (fp32 accum).
// Block: 128 i x 64 c, one K-split of 2048 j. 8 warps, 16 i-rows per warp.
// ---------------------------------------------------------------------------
__global__ __launch_bounds__(256) void gat_attn(const int* __restrict__ adj) {
    __shared__ __align__(16) char sA[BM * 128];     // P fp16, swizzled 16B segs
    __shared__ __align__(16) char sB[KC * 128];     // Wh fp16 [j][c], swizzled
    __shared__ __align__(16) float s2s[KS];
    __shared__ float psums[256];

    int t = threadIdx.x;
    int lane = t & 31, warp = t >> 5;
    int i0 = blockIdx.x * BM;
    int sp = blockIdx.y;
    size_t jbase = (size_t)sp * KS;

#pragma unroll
    for (int q = 0; q < 2; q++)
        ((float4*)s2s)[t + q * 256] = ((const float4*)(g_s2 + jbase))[t + q * 256];

    int iloc = t >> 1, half = t & 1;
    float s1v = g_s1[i0 + iloc];
    float zM = s1v + g_M2;
    float mrow = zM > 0.f ? zM : ALPHA * zM;
    const int4* arow = (const int4*)(adj + (size_t)(i0 + iloc) * N_NODES + jbase);
    float psum = 0.f;

    float acc[8][4];
#pragma unroll
    for (int n = 0; n < 8; n++)
#pragma unroll
        for (int k = 0; k < 4; k++) acc[n][k] = 0.f;

    uint32_t sA_u = smem_u32(sA), sB_u = smem_u32(sB);
    int r_a = warp * 16 + (lane & 15);
    int seg_hi = lane >> 4;                // 0 or 1

    __syncthreads();

    for (int ck = 0; ck < NCHUNK; ck++) {
        // ---- stage B tile: Wh rows jbase+ck*64 .. +63, fp16, swizzled ----
        {
            int j = t >> 2;
            int sg = (t & 3) << 1;
            const uint4* src = (const uint4*)(g_Whh + (jbase + (size_t)ck * KC + j) * F_OUT);
            uint4 v0 = src[sg];
            uint4 v1 = src[sg + 1];
            *(uint4*)(sB + j * 128 + ((sg ^ (j & 7)) << 4)) = v0;
            *(uint4*)(sB + j * 128 + (((sg + 1) ^ (j & 7)) << 4)) = v1;
        }
        // ---- P tile: thread covers row iloc, j = half*32 + q*8 .. +7 ----
#pragma unroll
        for (int q = 0; q < 4; q++) {
            int jj = half * 32 + q * 8;
            int4 av0 = arow[ck * 16 + (jj >> 2)];
            int4 av1 = arow[ck * 16 + (jj >> 2) + 1];
            float4 sv0 = *(const float4*)(s2s + ck * KC + jj);
            float4 sv1 = *(const float4*)(s2s + ck * KC + jj + 4);
            float z0 = s1v + sv0.x, z1 = s1v + sv0.y, z2 = s1v + sv0.z, z3 = s1v + sv0.w;
            float z4 = s1v + sv1.x, z5 = s1v + sv1.y, z6 = s1v + sv1.z, z7 = s1v + sv1.w;
            float e0 = z0 > 0.f ? z0 : ALPHA * z0;
            float e1 = z1 > 0.f ? z1 : ALPHA * z1;
            float e2 = z2 > 0.f ? z2 : ALPHA * z2;
            float e3 = z3 > 0.f ? z3 : ALPHA * z3;
            float e4 = z4 > 0.f ? z4 : ALPHA * z4;
            float e5 = z5 > 0.f ? z5 : ALPHA * z5;
            float e6 = z6 > 0.f ? z6 : ALPHA * z6;
            float e7 = z7 > 0.f ? z7 : ALPHA * z7;
            float p0 = (av0.x > 0) ? __expf(e0 - mrow) : 0.f;
            float p1 = (av0.y > 0) ? __expf(e1 - mrow) : 0.f;
            float p2 = (av0.z > 0) ? __expf(e2 - mrow) : 0.f;
            float p3 = (av0.w > 0) ? __expf(e3 - mrow) : 0.f;
            float p4 = (av1.x > 0) ? __expf(e4 - mrow) : 0.f;
            float p5 = (av1.y > 0) ? __expf(e5 - mrow) : 0.f;
            float p6 = (av1.z > 0) ? __expf(e6 - mrow) : 0.f;
            float p7 = (av1.w > 0) ? __expf(e7 - mrow) : 0.f;
            psum += ((p0 + p1) + (p2 + p3)) + ((p4 + p5) + (p6 + p7));
            uint4 pw;
            pw.x = cvt_f16x2(p0, p1);
            pw.y = cvt_f16x2(p2, p3);
            pw.z = cvt_f16x2(p4, p5);
            pw.w = cvt_f16x2(p6, p7);
            int sg = (half << 2) + q;
            *(uint4*)(sA + iloc * 128 + ((sg ^ (iloc & 7)) << 4)) = pw;
        }
        __syncthreads();

        // ---- MMA: 16i x 64c x 64j per warp ----
#pragma unroll
        for (int kt = 0; kt < 4; kt++) {
            uint32_t a0, a1, a2, a3;
            {
                int seg = kt * 2 + seg_hi;
                ldsm_x4(a0, a1, a2, a3, sA_u + r_a * 128 + ((seg ^ (r_a & 7)) << 4));
            }
            int r_b = kt * 16 + (lane & 15);
            uint32_t b[4][4];
#pragma unroll
            for (int ng = 0; ng < 4; ng++) {
                int seg = ng * 2 + seg_hi;
                ldsm_x4_t(b[ng][0], b[ng][1], b[ng][2], b[ng][3],
                          sB_u + r_b * 128 + ((seg ^ (r_b & 7)) << 4));
            }
#pragma unroll
            for (int ng = 0; ng < 4; ng++) {
                mma_f16(acc[2 * ng],     a0, a1, a2, a3, b[ng][0], b[ng][1]);
                mma_f16(acc[2 * ng + 1], a0, a1, a2, a3, b[ng][2], b[ng][3]);
            }
        }
        __syncthreads();
    }

    // ---- epilogue: write partial accumulators + row sums ----
    psums[t] = psum;
    __syncthreads();

    int row = warp * 16 + (lane >> 2);
    int cb = (lane & 3) * 2;
    float* pb = &g_pacc[sp][i0][0];
#pragma unroll
    for (int n = 0; n < 8; n++) {
        *(float2*)(pb + (size_t)row * F_OUT + n * 8 + cb)       = make_float2(acc[n][0], acc[n][1]);
        *(float2*)(pb + (size_t)(row + 8) * F_OUT + n * 8 + cb) = make_float2(acc[n][2], acc[n][3]);
    }
    if (t < 128) g_pl[sp][i0 + t] = psums[2 * t] + psums[2 * t + 1];
}

// ---------------------------------------------------------------------------
// Kernel 4: merge splits, normalize, elu.
// ---------------------------------------------------------------------------
__global__ __launch_bounds__(256) void gat_merge(float* __restrict__ out) {
    int idx = blockIdx.x * 256 + threadIdx.x;
    int i = idx >> 6;
    float v = 0.f, l = 0.f;
#pragma unroll
    for (int s = 0; s < SPLITS; s++) {
        v += g_pacc[s][i][idx & 63];
        l += g_pl[s][i];
    }
    float r = v / l;
    out[idx] = r > 0.f ? r : expm1f(r);
}

// ---------------------------------------------------------------------------
extern "C" void kernel_launch(void* const* d_in, const int* in_sizes, int n_in,
                              void* d_out, int out_size) {
    const float* h   = (const float*)d_in[0];
    const float* W   = (const float*)d_in[1];
    const float* a   = (const float*)d_in[2];
    const int*   adj = (const int*)d_in[3];
    float* out = (float*)d_out;

    gat_gemm<<<N_NODES / 32, 256>>>(h, W);
    gat_s<<<N_NODES / 8, 256>>>(a);
    gat_max<<<1, 256>>>();
    gat_attn<<<dim3(N_NODES / BM, SPLITS), 256>>>(adj);
    gat_merge<<<N_NODES * F_OUT / 256, 256>>>(out);
}

// round 9
// speedup vs baseline: 6.3668x; 1.5414x over previous
#include <cuda_runtime.h>
#include <cuda_fp16.h>
#include <cstdint>

#define N_NODES 8192
#define F_IN    512
#define F_OUT   64
#define ALPHA   0.2f
#define BM      128                  // i rows per attn block (8 warps x 16)
#define KC      64                   // j per chunk
#define SPLITS  16
#define KS      (N_NODES / SPLITS)   // 512
#define NCHUNK  (KS / KC)            // 8
#define L2E     1.4426950408889634f

__device__ __align__(16) float  g_Wh[N_NODES * F_OUT];
__device__ __align__(16) __half g_Whh[N_NODES * F_OUT];   // row-major fp16
__device__ __align__(16) uint4  g_WhF[(N_NODES / 16) * 4 * 32];  // B-fragment layout, 1MB
__device__ __align__(16) float  g_s1[N_NODES];
__device__ __align__(16) float  g_s2[N_NODES];
__device__ float g_M2;
__device__ __align__(16) float g_pacc[SPLITS][N_NODES][F_OUT];
__device__ __align__(16) float g_pl[SPLITS][N_NODES];

// ---------------- helpers ----------------
__device__ __forceinline__ uint32_t cvt_f16x2(float lo, float hi) {
    uint32_t r;
    asm("cvt.rn.f16x2.f32 %0, %1, %2;" : "=r"(r) : "f"(hi), "f"(lo));
    return r;
}
__device__ __forceinline__ float ex2f(float x) {
    float r;
    asm("ex2.approx.ftz.f32 %0, %1;" : "=f"(r) : "f"(x));
    return r;
}
__device__ __forceinline__ void mma_f16(float* c, uint32_t a0, uint32_t a1, uint32_t a2, uint32_t a3,
                                        uint32_t b0, uint32_t b1) {
    asm volatile(
        "mma.sync.aligned.m16n8k16.row.col.f32.f16.f16.f32 "
        "{%0,%1,%2,%3}, {%4,%5,%6,%7}, {%8,%9}, {%0,%1,%2,%3};"
        : "+f"(c[0]), "+f"(c[1]), "+f"(c[2]), "+f"(c[3])
        : "r"(a0), "r"(a1), "r"(a2), "r"(a3), "r"(b0), "r"(b1));
}

// ---------------------------------------------------------------------------
// Kernel 1: Wh = h @ W (fp32) + fp16 copy. Register-prefetch double buffer.
// ---------------------------------------------------------------------------
__global__ __launch_bounds__(256) void gat_gemm(const float* __restrict__ h,
                                                const float* __restrict__ W) {
    __shared__ float hs[32][36];
    __shared__ float Ws[32][64];
    int t = threadIdx.x;
    int c = t & 63;
    int rg = t >> 6;
    int row0 = blockIdx.x * 32;

    int hr = t >> 3, hk4 = (t & 7) << 2;
    int wk = t >> 4, wc4 = (t & 15) << 2;

    float acc[8];
#pragma unroll
    for (int r = 0; r < 8; r++) acc[r] = 0.f;

    float4 hreg = *(const float4*)(h + (size_t)(row0 + hr) * F_IN + hk4);
    float4 wreg0 = *(const float4*)(W + (size_t)wk * F_OUT + wc4);
    float4 wreg1 = *(const float4*)(W + (size_t)(wk + 16) * F_OUT + wc4);

    for (int kt = 0; kt < F_IN; kt += 32) {
        *(float4*)&hs[hr][hk4] = hreg;
        *(float4*)&Ws[wk][wc4] = wreg0;
        *(float4*)&Ws[wk + 16][wc4] = wreg1;
        __syncthreads();
        if (kt + 32 < F_IN) {
            hreg = *(const float4*)(h + (size_t)(row0 + hr) * F_IN + kt + 32 + hk4);
            wreg0 = *(const float4*)(W + (size_t)(kt + 32 + wk) * F_OUT + wc4);
            wreg1 = *(const float4*)(W + (size_t)(kt + 32 + wk + 16) * F_OUT + wc4);
        }
#pragma unroll
        for (int kk = 0; kk < 32; kk++) {
            float w = Ws[kk][c];
#pragma unroll
            for (int r = 0; r < 8; r++)
                acc[r] += hs[rg * 8 + r][kk] * w;
        }
        __syncthreads();
    }
#pragma unroll
    for (int r = 0; r < 8; r++) {
        int row = row0 + rg * 8 + r;
        g_Wh[(size_t)row * F_OUT + c] = acc[r];
        g_Whh[(size_t)row * F_OUT + c] = __float2half_rn(acc[r]);
    }
}

// ---------------------------------------------------------------------------
// Kernel 2: s1, s2 (one warp per row)
// ---------------------------------------------------------------------------
__global__ __launch_bounds__(256) void gat_s(const float* __restrict__ a) {
    int warp = (blockIdx.x * blockDim.x + threadIdx.x) >> 5;
    int lane = threadIdx.x & 31;
    float w0 = g_Wh[(size_t)warp * F_OUT + lane];
    float w1 = g_Wh[(size_t)warp * F_OUT + 32 + lane];
    float p1 = w0 * a[lane] + w1 * a[lane + 32];
    float p2 = w0 * a[64 + lane] + w1 * a[96 + lane];
#pragma unroll
    for (int m = 16; m > 0; m >>= 1) {
        p1 += __shfl_xor_sync(0xffffffffu, p1, m);
        p2 += __shfl_xor_sync(0xffffffffu, p2, m);
    }
    if (lane == 0) { g_s1[warp] = p1; g_s2[warp] = p2; }
}

__global__ void gat_max() {
    __shared__ float red[256];
    int t = threadIdx.x;
    float m = -1e30f;
    for (int i = t; i < N_NODES; i += 256) m = fmaxf(m, g_s2[i]);
    red[t] = m;
    __syncthreads();
#pragma unroll
    for (int s = 128; s > 0; s >>= 1) {
        if (t < s) red[t] = fmaxf(red[t], red[t + s]);
        __syncthreads();
    }
    if (t == 0) g_M2 = red[0];
}

// ---------------------------------------------------------------------------
// Kernel 2c: build B-fragment layout of Wh (fp16).
// uint4 per (jt, p, lane): {b0(ng=2p), b1(2p), b0(2p+1), b1(2p+1)}
//   b0(ng) = {Wh[jt*16+2c][8ng+g], Wh[jt*16+2c+1][8ng+g]},  b1 = rows +8,+9
// ---------------------------------------------------------------------------
__global__ __launch_bounds__(256) void gat_frag() {
    int idx = blockIdx.x * 256 + threadIdx.x;      // 65536
    int lane = idx & 31;
    int p = (idx >> 5) & 3;
    int jt = idx >> 7;
    int g = lane >> 2, c = lane & 3;
    size_t r = (size_t)jt * 16 + 2 * c;
    int n0 = 16 * p + g, n1 = n0 + 8;
    const __half* w = g_Whh;
    __half2 x = __halves2half2(w[r * 64 + n0],       w[(r + 1) * 64 + n0]);
    __half2 y = __halves2half2(w[(r + 8) * 64 + n0], w[(r + 9) * 64 + n0]);
    __half2 z = __halves2half2(w[r * 64 + n1],       w[(r + 1) * 64 + n1]);
    __half2 v = __halves2half2(w[(r + 8) * 64 + n1], w[(r + 9) * 64 + n1]);
    uint4 o;
    o.x = *(uint32_t*)&x; o.y = *(uint32_t*)&y; o.z = *(uint32_t*)&z; o.w = *(uint32_t*)&v;
    g_WhF[idx] = o;
}

// ---------------------------------------------------------------------------
// Kernel 3: masked-softmax GEMM, P built directly in mma A-fragment regs.
// Block: 128 i (8 warps x 16) x 64 c, one K-split of 512 j. No mainloop syncs.
// ---------------------------------------------------------------------------
__global__ __launch_bounds__(256, 2) void gat_attn(const int* __restrict__ adj) {
    __shared__ __align__(16) float s2s[KS];        // pre-scaled by log2(e)

    int t = threadIdx.x;
    int lane = t & 31, warp = t >> 5;
    int g = lane >> 2, c = lane & 3;
    int i0 = blockIdx.x * BM;
    int sp = blockIdx.y;
    size_t jbase = (size_t)sp * KS;

    s2s[t]       = g_s2[jbase + t] * L2E;
    s2s[t + 256] = g_s2[jbase + t + 256] * L2E;
    __syncthreads();

    int r0 = i0 + warp * 16 + g;                   // rows r0 and r0+8
    float s10 = g_s1[r0], s11 = g_s1[r0 + 8];
    float M2 = g_M2;
    float zz0 = s10 + M2, zz1 = s11 + M2;
    float m0 = fmaxf(zz0, ALPHA * zz0);
    float m1 = fmaxf(zz1, ALPHA * zz1);
    float u0 = (s10 - m0) * L2E, v0 = (ALPHA * s10 - m0) * L2E;
    float u1 = (s11 - m1) * L2E, v1 = (ALPHA * s11 - m1) * L2E;

    const int* adjA = adj + (size_t)r0 * N_NODES + jbase;
    const int* adjB = adj + (size_t)(r0 + 8) * N_NODES + jbase;
    const uint4* whf = g_WhF + (jbase >> 4) * 128 + lane;

    float acc[8][4];
#pragma unroll
    for (int n = 0; n < 8; n++)
#pragma unroll
        for (int k = 0; k < 4; k++) acc[n][k] = 0.f;
    float ps0 = 0.f, ps1 = 0.f;

#pragma unroll 1
    for (int ck = 0; ck < NCHUNK; ck++) {
#pragma unroll
        for (int kt = 0; kt < 4; kt++) {
            int cb = ck * KC + kt * 16;
            int o1 = cb + 2 * c, o2 = o1 + 8;
            int2 aA1 = *(const int2*)(adjA + o1);
            int2 aA2 = *(const int2*)(adjA + o2);
            int2 aB1 = *(const int2*)(adjB + o1);
            int2 aB2 = *(const int2*)(adjB + o2);
            float2 t1 = *(const float2*)(s2s + o1);
            float2 t2 = *(const float2*)(s2s + o2);

            float q1x = ALPHA * t1.x, q1y = ALPHA * t1.y;
            float q2x = ALPHA * t2.x, q2y = ALPHA * t2.y;

            float p00 = (aA1.x > 0) ? ex2f(fmaxf(u0 + t1.x, v0 + q1x)) : 0.f;
            float p01 = (aA1.y > 0) ? ex2f(fmaxf(u0 + t1.y, v0 + q1y)) : 0.f;
            float p02 = (aA2.x > 0) ? ex2f(fmaxf(u0 + t2.x, v0 + q2x)) : 0.f;
            float p03 = (aA2.y > 0) ? ex2f(fmaxf(u0 + t2.y, v0 + q2y)) : 0.f;
            float p10 = (aB1.x > 0) ? ex2f(fmaxf(u1 + t1.x, v1 + q1x)) : 0.f;
            float p11 = (aB1.y > 0) ? ex2f(fmaxf(u1 + t1.y, v1 + q1y)) : 0.f;
            float p12 = (aB2.x > 0) ? ex2f(fmaxf(u1 + t2.x, v1 + q2x)) : 0.f;
            float p13 = (aB2.y > 0) ? ex2f(fmaxf(u1 + t2.y, v1 + q2y)) : 0.f;

            ps0 += (p00 + p01) + (p02 + p03);
            ps1 += (p10 + p11) + (p12 + p13);

            uint32_t a0 = cvt_f16x2(p00, p01);
            uint32_t a1 = cvt_f16x2(p10, p11);
            uint32_t a2 = cvt_f16x2(p02, p03);
            uint32_t a3 = cvt_f16x2(p12, p13);

            const uint4* bp = whf + (size_t)(cb >> 4) * 128;
            uint4 B0 = bp[0];
            uint4 B1 = bp[32];
            uint4 B2 = bp[64];
            uint4 B3 = bp[96];

            mma_f16(acc[0], a0, a1, a2, a3, B0.x, B0.y);
            mma_f16(acc[1], a0, a1, a2, a3, B0.z, B0.w);
            mma_f16(acc[2], a0, a1, a2, a3, B1.x, B1.y);
            mma_f16(acc[3], a0, a1, a2, a3, B1.z, B1.w);
            mma_f16(acc[4], a0, a1, a2, a3, B2.x, B2.y);
            mma_f16(acc[5], a0, a1, a2, a3, B2.z, B2.w);
            mma_f16(acc[6], a0, a1, a2, a3, B3.x, B3.y);
            mma_f16(acc[7], a0, a1, a2, a3, B3.z, B3.w);
        }
    }

    // row sums: reduce over quad (lanes sharing g)
    ps0 += __shfl_xor_sync(0xffffffffu, ps0, 1);
    ps0 += __shfl_xor_sync(0xffffffffu, ps0, 2);
    ps1 += __shfl_xor_sync(0xffffffffu, ps1, 1);
    ps1 += __shfl_xor_sync(0xffffffffu, ps1, 2);
    if (c == 0) {
        g_pl[sp][r0] = ps0;
        g_pl[sp][r0 + 8] = ps1;
    }

    float* pb = &g_pacc[sp][0][0];
#pragma unroll
    for (int ng = 0; ng < 8; ng++) {
        *(float2*)(pb + (size_t)r0 * F_OUT + ng * 8 + 2 * c)       = make_float2(acc[ng][0], acc[ng][1]);
        *(float2*)(pb + (size_t)(r0 + 8) * F_OUT + ng * 8 + 2 * c) = make_float2(acc[ng][2], acc[ng][3]);
    }
}

// ---------------------------------------------------------------------------
// Kernel 4: merge splits, normalize, elu.
// ---------------------------------------------------------------------------
__global__ __launch_bounds__(256) void gat_merge(float* __restrict__ out) {
    int idx = blockIdx.x * 256 + threadIdx.x;
    int i = idx >> 6;
    float v = 0.f, l = 0.f;
#pragma unroll
    for (int s = 0; s < SPLITS; s++) {
        v += g_pacc[s][i][idx & 63];
        l += g_pl[s][i];
    }
    float r = v / l;
    out[idx] = r > 0.f ? r : expm1f(r);
}

// ---------------------------------------------------------------------------
extern "C" void kernel_launch(void* const* d_in, const int* in_sizes, int n_in,
                              void* d_out, int out_size) {
    const float* h   = (const float*)d_in[0];
    const float* W   = (const float*)d_in[1];
    const float* a   = (const float*)d_in[2];
    const int*   adj = (const int*)d_in[3];
    float* out = (float*)d_out;

    gat_gemm<<<N_NODES / 32, 256>>>(h, W);
    gat_s<<<N_NODES / 8, 256>>>(a);
    gat_max<<<1, 256>>>();
    gat_frag<<<(N_NODES / 16) * 4 * 32 / 256, 256>>>();
    gat_attn<<<dim3(N_NODES / BM, SPLITS), 256>>>(adj);
    gat_merge<<<N_NODES * F_OUT / 256, 256>>>(out);
}

// round 11
// speedup vs baseline: 7.2198x; 1.1340x over previous
#include <cuda_runtime.h>
#include <cuda_fp16.h>
#include <cstdint>

#define N_NODES 8192
#define F_IN    512
#define F_OUT   64
#define ALPHA   0.2f
#define BM      128                  // i rows per attn block (8 warps x 16)
#define SPLITS  8
#define KS      (N_NODES / SPLITS)   // 1024
#define NSTEP   (KS / 16)            // 64
#define L2E     1.4426950408889634f

__device__ __align__(16) uint4  g_WhF[(N_NODES / 16) * 4 * 32];  // B-fragment layout, 1MB
__device__ __align__(16) float  g_s1[N_NODES];
__device__ __align__(16) float  g_s2[N_NODES];
__device__ int g_M2i;                // max(0, max s2) as int-reinterp float (atomicMax, idempotent)
__device__ __align__(16) float  g_pacc[SPLITS][N_NODES][F_OUT];
__device__ __align__(16) float  g_pl[SPLITS][N_NODES];

// ---------------- helpers ----------------
__device__ __forceinline__ uint32_t cvt_f16x2(float lo, float hi) {
    uint32_t r;
    asm("cvt.rn.f16x2.f32 %0, %1, %2;" : "=r"(r) : "f"(hi), "f"(lo));
    return r;
}
__device__ __forceinline__ float ex2f(float x) {
    float r;
    asm("ex2.approx.ftz.f32 %0, %1;" : "=f"(r) : "f"(x));
    return r;
}
__device__ __forceinline__ void mma_f16(float* c, uint32_t a0, uint32_t a1, uint32_t a2, uint32_t a3,
                                        uint32_t b0, uint32_t b1) {
    asm volatile(
        "mma.sync.aligned.m16n8k16.row.col.f32.f16.f16.f32 "
        "{%0,%1,%2,%3}, {%4,%5,%6,%7}, {%8,%9}, {%0,%1,%2,%3};"
        : "+f"(c[0]), "+f"(c[1]), "+f"(c[2]), "+f"(c[3])
        : "r"(a0), "r"(a1), "r"(a2), "r"(a3), "r"(b0), "r"(b1));
}

// ---------------------------------------------------------------------------
// Kernel 1: Wh = h @ W, fused epilogue:
//   - s1/s2 = Wh . a1/a2 (warp shfl reduce, fp32) + atomicMax for M2
//   - g_WhF B-fragment fp16 layout (smem staging, coalesced 16B stores)
// ---------------------------------------------------------------------------
__global__ __launch_bounds__(256) void gat_gemm(const float* __restrict__ h,
                                                const float* __restrict__ W,
                                                const float* __restrict__ a) {
    __shared__ float hs[32][36];
    __shared__ float Ws[32][64];
    __shared__ __half whl[32][64];
    __shared__ float sred[4][2][8][2];   // [rg][warp-parity][r][s1|s2]

    int t = threadIdx.x;
    int c = t & 63;
    int rg = t >> 6;
    int lane = t & 31;
    int row0 = blockIdx.x * 32;

    int hr = t >> 3, hk4 = (t & 7) << 2;
    int wk = t >> 4, wc4 = (t & 15) << 2;

    float acc[8];
#pragma unroll
    for (int r = 0; r < 8; r++) acc[r] = 0.f;

    float4 hreg = *(const float4*)(h + (size_t)(row0 + hr) * F_IN + hk4);
    float4 wreg0 = *(const float4*)(W + (size_t)wk * F_OUT + wc4);
    float4 wreg1 = *(const float4*)(W + (size_t)(wk + 16) * F_OUT + wc4);

    for (int kt = 0; kt < F_IN; kt += 32) {
        *(float4*)&hs[hr][hk4] = hreg;
        *(float4*)&Ws[wk][wc4] = wreg0;
        *(float4*)&Ws[wk + 16][wc4] = wreg1;
        __syncthreads();
        if (kt + 32 < F_IN) {
            hreg = *(const float4*)(h + (size_t)(row0 + hr) * F_IN + kt + 32 + hk4);
            wreg0 = *(const float4*)(W + (size_t)(kt + 32 + wk) * F_OUT + wc4);
            wreg1 = *(const float4*)(W + (size_t)(kt + 32 + wk + 16) * F_OUT + wc4);
        }
#pragma unroll
        for (int kk = 0; kk < 32; kk += 4) {
            float w0 = Ws[kk][c], w1 = Ws[kk + 1][c], w2 = Ws[kk + 2][c], w3 = Ws[kk + 3][c];
#pragma unroll
            for (int r = 0; r < 8; r++) {
                float4 hv = *(const float4*)&hs[rg * 8 + r][kk];
                acc[r] = fmaf(hv.x, w0, acc[r]);
                acc[r] = fmaf(hv.y, w1, acc[r]);
                acc[r] = fmaf(hv.z, w2, acc[r]);
                acc[r] = fmaf(hv.w, w3, acc[r]);
            }
        }
        __syncthreads();
    }

    // ---- epilogue: fp16 staging + s1/s2 reduce ----
    float a1c = a[c], a2c = a[64 + c];
#pragma unroll
    for (int r = 0; r < 8; r++)
        whl[rg * 8 + r][c] = __float2half_rn(acc[r]);

#pragma unroll
    for (int r = 0; r < 8; r++) {
        float x1 = acc[r] * a1c;
        float x2 = acc[r] * a2c;
#pragma unroll
        for (int m = 16; m > 0; m >>= 1) {
            x1 += __shfl_xor_sync(0xffffffffu, x1, m);
            x2 += __shfl_xor_sync(0xffffffffu, x2, m);
        }
        if (lane == 0) {
            sred[rg][(t >> 5) & 1][r][0] = x1;
            sred[rg][(t >> 5) & 1][r][1] = x2;
        }
    }
    __syncthreads();
    if (t < 32) {
        float s1v = sred[t >> 3][0][t & 7][0] + sred[t >> 3][1][t & 7][0];
        float s2v = sred[t >> 3][0][t & 7][1] + sred[t >> 3][1][t & 7][1];
        g_s1[row0 + t] = s1v;
        g_s2[row0 + t] = s2v;
        // block max of s2 (clamped to >= 0) -> atomicMax (valid for non-neg floats)
        float mx = fmaxf(s2v, 0.f);
#pragma unroll
        for (int m = 16; m > 0; m >>= 1)
            mx = fmaxf(mx, __shfl_xor_sync(0xffffffffu, mx, m));
        if (t == 0) atomicMax(&g_M2i, __float_as_int(mx));
    }

    // ---- frag assembly: one uint4 per thread, coalesced ----
    {
        int jtl = t >> 7;                 // 0,1 : which 16-row tile
        int p = (t >> 5) & 3;             // n-group pair
        int l5 = t & 31;
        int gg = l5 >> 2, c4 = l5 & 3;
        int r = jtl * 16 + 2 * c4;
        int n0 = 16 * p + gg, n1 = n0 + 8;
        __half2 x = __halves2half2(whl[r][n0],     whl[r + 1][n0]);
        __half2 y = __halves2half2(whl[r + 8][n0], whl[r + 9][n0]);
        __half2 z = __halves2half2(whl[r][n1],     whl[r + 1][n1]);
        __half2 v = __halves2half2(whl[r + 8][n1], whl[r + 9][n1]);
        uint4 o;
        o.x = *(uint32_t*)&x; o.y = *(uint32_t*)&y;
        o.z = *(uint32_t*)&z; o.w = *(uint32_t*)&v;
        g_WhF[(size_t)(blockIdx.x * 2 + jtl) * 128 + p * 32 + l5] = o;
    }
}

// ---------------------------------------------------------------------------
// Kernel 2: masked-softmax GEMM, P built in mma A-fragment regs.
// Per-row shift m_i = lrelu(s1_i + M2) guarantees p <= 1 (fp16-safe).
// Row sums via ones-MMA. One-step-ahead prefetch. No mainloop syncs.
// ---------------------------------------------------------------------------
__global__ __launch_bounds__(256, 2) void gat_attn(const int* __restrict__ adj) {
    __shared__ __align__(16) float s2s[KS];      // s2 * log2(e)

    int t = threadIdx.x;
    int lane = t & 31, warp = t >> 5;
    int g = lane >> 2, c = lane & 3;
    int i0 = blockIdx.x * BM;
    int sp = blockIdx.y;
    size_t jbase = (size_t)sp * KS;

    {
        float4 sv = ((const float4*)(g_s2 + jbase))[t];
        sv.x *= L2E; sv.y *= L2E; sv.z *= L2E; sv.w *= L2E;
        ((float4*)s2s)[t] = sv;
    }
    __syncthreads();

    int r0 = i0 + warp * 16 + g;
    float M2 = __int_as_float(g_M2i);
    float s10 = g_s1[r0], s11 = g_s1[r0 + 8];
    float zz0 = s10 + M2, zz1 = s11 + M2;
    float m0 = fmaxf(zz0, ALPHA * zz0);
    float m1 = fmaxf(zz1, ALPHA * zz1);
    float u0 = (s10 - m0) * L2E, v0 = (ALPHA * s10 - m0) * L2E;
    float u1 = (s11 - m1) * L2E, v1 = (ALPHA * s11 - m1) * L2E;

    const int* adjA = adj + (size_t)r0 * N_NODES + jbase + 2 * c;
    const int* adjB = adjA + (size_t)8 * N_NODES;
    const uint4* whf = g_WhF + (jbase >> 4) * 128 + lane;
    const float* s2p = s2s + 2 * c;

    float acc[8][4];
#pragma unroll
    for (int n = 0; n < 8; n++)
#pragma unroll
        for (int k = 0; k < 4; k++) acc[n][k] = 0.f;
    float accl[4] = {0.f, 0.f, 0.f, 0.f};
    const uint32_t ONE2 = 0x3C003C00u;

    int2 aA1[2], aA2[2], aB1[2], aB2[2];
    uint4 Bf[2][4];
    aA1[0] = *(const int2*)(adjA);
    aA2[0] = *(const int2*)(adjA + 8);
    aB1[0] = *(const int2*)(adjB);
    aB2[0] = *(const int2*)(adjB + 8);
    Bf[0][0] = whf[0]; Bf[0][1] = whf[32]; Bf[0][2] = whf[64]; Bf[0][3] = whf[96];

#pragma unroll 2
    for (int step = 0; step < NSTEP; step++) {
        int cur = step & 1, nxt = cur ^ 1;
        if (step + 1 < NSTEP) {
            int off = (step + 1) * 16;
            aA1[nxt] = *(const int2*)(adjA + off);
            aA2[nxt] = *(const int2*)(adjA + off + 8);
            aB1[nxt] = *(const int2*)(adjB + off);
            aB2[nxt] = *(const int2*)(adjB + off + 8);
            const uint4* bp = whf + (size_t)(step + 1) * 128;
            Bf[nxt][0] = bp[0]; Bf[nxt][1] = bp[32]; Bf[nxt][2] = bp[64]; Bf[nxt][3] = bp[96];
        }

        float2 t1 = *(const float2*)(s2p + step * 16);
        float2 t2 = *(const float2*)(s2p + step * 16 + 8);
        float q1x = ALPHA * t1.x, q1y = ALPHA * t1.y;
        float q2x = ALPHA * t2.x, q2y = ALPHA * t2.y;

        float p00 = (aA1[cur].x > 0) ? ex2f(fmaxf(u0 + t1.x, v0 + q1x)) : 0.f;
        float p01 = (aA1[cur].y > 0) ? ex2f(fmaxf(u0 + t1.y, v0 + q1y)) : 0.f;
        float p02 = (aA2[cur].x > 0) ? ex2f(fmaxf(u0 + t2.x, v0 + q2x)) : 0.f;
        float p03 = (aA2[cur].y > 0) ? ex2f(fmaxf(u0 + t2.y, v0 + q2y)) : 0.f;
        float p10 = (aB1[cur].x > 0) ? ex2f(fmaxf(u1 + t1.x, v1 + q1x)) : 0.f;
        float p11 = (aB1[cur].y > 0) ? ex2f(fmaxf(u1 + t1.y, v1 + q1y)) : 0.f;
        float p12 = (aB2[cur].x > 0) ? ex2f(fmaxf(u1 + t2.x, v1 + q2x)) : 0.f;
        float p13 = (aB2[cur].y > 0) ? ex2f(fmaxf(u1 + t2.y, v1 + q2y)) : 0.f;

        uint32_t a0 = cvt_f16x2(p00, p01);
        uint32_t a1 = cvt_f16x2(p10, p11);
        uint32_t a2 = cvt_f16x2(p02, p03);
        uint32_t a3 = cvt_f16x2(p12, p13);

        mma_f16(acc[0], a0, a1, a2, a3, Bf[cur][0].x, Bf[cur][0].y);
        mma_f16(acc[1], a0, a1, a2, a3, Bf[cur][0].z, Bf[cur][0].w);
        mma_f16(acc[2], a0, a1, a2, a3, Bf[cur][1].x, Bf[cur][1].y);
        mma_f16(acc[3], a0, a1, a2, a3, Bf[cur][1].z, Bf[cur][1].w);
        mma_f16(acc[4], a0, a1, a2, a3, Bf[cur][2].x, Bf[cur][2].y);
        mma_f16(acc[5], a0, a1, a2, a3, Bf[cur][2].z, Bf[cur][2].w);
        mma_f16(acc[6], a0, a1, a2, a3, Bf[cur][3].x, Bf[cur][3].y);
        mma_f16(acc[7], a0, a1, a2, a3, Bf[cur][3].z, Bf[cur][3].w);
        mma_f16(accl,   a0, a1, a2, a3, ONE2, ONE2);
    }

    if (c == 0) {
        g_pl[sp][r0] = accl[0];
        g_pl[sp][r0 + 8] = accl[2];
    }
    float* pb = &g_pacc[sp][0][0];
#pragma unroll
    for (int ng = 0; ng < 8; ng++) {
        *(float2*)(pb + (size_t)r0 * F_OUT + ng * 8 + 2 * c)       = make_float2(acc[ng][0], acc[ng][1]);
        *(float2*)(pb + (size_t)(r0 + 8) * F_OUT + ng * 8 + 2 * c) = make_float2(acc[ng][2], acc[ng][3]);
    }
}

// ---------------------------------------------------------------------------
// Kernel 3: merge splits, normalize, elu. (Split weights identical per split
// since all splits share the same per-row shift -> plain sums are exact.)
// ---------------------------------------------------------------------------
__global__ __launch_bounds__(256) void gat_merge(float* __restrict__ out) {
    int idx = blockIdx.x * 256 + threadIdx.x;
    int i = idx >> 6;
    float v = 0.f, l = 0.f;
#pragma unroll
    for (int s = 0; s < SPLITS; s++) {
        v += g_pacc[s][i][idx & 63];
        l += g_pl[s][i];
    }
    float r = v / l;
    out[idx] = r > 0.f ? r : expm1f(r);
}

// ---------------------------------------------------------------------------
extern "C" void kernel_launch(void* const* d_in, const int* in_sizes, int n_in,
                              void* d_out, int out_size) {
    const float* h   = (const float*)d_in[0];
    const float* W   = (const float*)d_in[1];
    const float* a   = (const float*)d_in[2];
    const int*   adj = (const int*)d_in[3];
    float* out = (float*)d_out;

    gat_gemm<<<N_NODES / 32, 256>>>(h, W, a);
    gat_attn<<<dim3(N_NODES / BM, SPLITS), 256>>>(adj);
    gat_merge<<<N_NODES * F_OUT / 256, 256>>>(out);
}

// round 14
// speedup vs baseline: 8.0236x; 1.1113x over previous
#include <cuda_runtime.h>
#include <cuda_fp16.h>
#include <cstdint>

#define N_NODES 8192
#define F_IN    512
#define F_OUT   64
#define ALPHA   0.2f
#define BM      128                  // i rows per attn block (8 warps x 16)
#define SPLITS  8
#define KS      (N_NODES / SPLITS)   // 1024
#define NSTEP   (KS / 16)            // 64
#define L2E     1.4426950408889634f
#define GROWS   64                   // rows per gemm block
#define KTILES  (F_IN / 64)          // 8

__device__ __align__(16) uint4  g_WhF[(N_NODES / 16) * 4 * 32];  // B-fragment layout, 1MB
__device__ __align__(16) float  g_s1[N_NODES];
__device__ __align__(16) float  g_s2[N_NODES];
__device__ int g_M2i;                // max(0, max s2) as int-reinterp float (atomicMax, idempotent)
__device__ __align__(16) float  g_pacc[SPLITS][N_NODES][F_OUT];
__device__ __align__(16) float  g_pl[SPLITS][N_NODES];

// ---------------- helpers ----------------
__device__ __forceinline__ uint32_t smem_u32(const void* p) {
    uint32_t a;
    asm("{ .reg .u64 t; cvta.to.shared.u64 t, %1; cvt.u32.u64 %0, t; }" : "=r"(a) : "l"(p));
    return a;
}
__device__ __forceinline__ uint32_t cvt_f16x2(float lo, float hi) {
    uint32_t r;
    asm("cvt.rn.f16x2.f32 %0, %1, %2;" : "=r"(r) : "f"(hi), "f"(lo));
    return r;
}
__device__ __forceinline__ float ex2f(float x) {
    float r;
    asm("ex2.approx.ftz.f32 %0, %1;" : "=f"(r) : "f"(x));
    return r;
}
__device__ __forceinline__ void ldsm_x4(uint32_t& r0, uint32_t& r1, uint32_t& r2, uint32_t& r3, uint32_t addr) {
    asm volatile("ldmatrix.sync.aligned.m8n8.x4.shared.b16 {%0,%1,%2,%3}, [%4];"
                 : "=r"(r0), "=r"(r1), "=r"(r2), "=r"(r3) : "r"(addr));
}
__device__ __forceinline__ void ldsm_x4_t(uint32_t& r0, uint32_t& r1, uint32_t& r2, uint32_t& r3, uint32_t addr) {
    asm volatile("ldmatrix.sync.aligned.m8n8.x4.trans.shared.b16 {%0,%1,%2,%3}, [%4];"
                 : "=r"(r0), "=r"(r1), "=r"(r2), "=r"(r3) : "r"(addr));
}
__device__ __forceinline__ void mma_f16(float* c, uint32_t a0, uint32_t a1, uint32_t a2, uint32_t a3,
                                        uint32_t b0, uint32_t b1) {
    asm volatile(
        "mma.sync.aligned.m16n8k16.row.col.f32.f16.f16.f32 "
        "{%0,%1,%2,%3}, {%4,%5,%6,%7}, {%8,%9}, {%0,%1,%2,%3};"
        : "+f"(c[0]), "+f"(c[1]), "+f"(c[2]), "+f"(c[3])
        : "r"(a0), "r"(a1), "r"(a2), "r"(a3), "r"(b0), "r"(b1));
}
__device__ __forceinline__ void sts_cvt16(char* base, int row, int s0,
                                          float4 v0, float4 v1, float4 v2, float4 v3) {
    uint4 o1, o2;
    o1.x = cvt_f16x2(v0.x, v0.y); o1.y = cvt_f16x2(v0.z, v0.w);
    o1.z = cvt_f16x2(v1.x, v1.y); o1.w = cvt_f16x2(v1.z, v1.w);
    o2.x = cvt_f16x2(v2.x, v2.y); o2.y = cvt_f16x2(v2.z, v2.w);
    o2.z = cvt_f16x2(v3.x, v3.y); o2.w = cvt_f16x2(v3.z, v3.w);
    *(uint4*)(base + row * 128 + (((s0    ) ^ (row & 7)) << 4)) = o1;
    *(uint4*)(base + row * 128 + (((s0 + 1) ^ (row & 7)) << 4)) = o2;
}

// ---------------------------------------------------------------------------
// Kernel 1: Wh = h @ W via fp16 mma.sync (fp32->fp16 convert during staging).
// 64 rows/block, grid 128, KTILES=8 k-tiles of 64. Fused epilogue:
// s1/s2 (fp32), M2 atomicMax, B-fragment assembly.
// ---------------------------------------------------------------------------
__global__ __launch_bounds__(256) void gat_gemm(const float* __restrict__ h,
                                                const float* __restrict__ W,
                                                const float* __restrict__ a) {
    __shared__ __align__(16) char sH[2][GROWS * 128];   // fp16 [row][k64], swizzled
    __shared__ __align__(16) char sW[2][64 * 128];      // fp16 [k64][n64], swizzled
    __shared__ __half whl[GROWS][72];
    __shared__ float a_s[128];

    int t = threadIdx.x;
    int lane = t & 31, warp = t >> 5;
    int mw = warp & 3, nh = warp >> 2;
    int seg_hi = lane >> 4;
    int row0 = blockIdx.x * GROWS;

    if (t < 128) a_s[t] = a[t];

    int srow = t >> 2, q = t & 3;           // staging: 4 threads per row
    const float4* hsrc = (const float4*)(h + (size_t)(row0 + srow) * F_IN + q * 16);
    const float4* wsrc = (const float4*)(W + (size_t)srow * F_OUT + q * 16);

    float4 hr[4], wr[4];
#pragma unroll
    for (int j = 0; j < 4; j++) { hr[j] = hsrc[j]; wr[j] = wsrc[j]; }
    sts_cvt16(sH[0], srow, q * 2, hr[0], hr[1], hr[2], hr[3]);
    sts_cvt16(sW[0], srow, q * 2, wr[0], wr[1], wr[2], wr[3]);
    __syncthreads();

    float acc[4][4];
#pragma unroll
    for (int n = 0; n < 4; n++)
#pragma unroll
        for (int k = 0; k < 4; k++) acc[n][k] = 0.f;

    int r_a = mw * 16 + (lane & 15);
    int r_bb = lane & 15;

#pragma unroll 1
    for (int kt = 0; kt < KTILES; kt++) {
        int buf = kt & 1;
        if (kt + 1 < KTILES) {
#pragma unroll
            for (int j = 0; j < 4; j++) {
                hr[j] = hsrc[(kt + 1) * 16 + j];        // +64 floats per tile
                wr[j] = wsrc[(kt + 1) * 1024 + j];      // +64 W rows per tile
            }
        }
        uint32_t hb = smem_u32(sH[buf]);
        uint32_t wb = smem_u32(sW[buf]);
#pragma unroll
        for (int kl = 0; kl < 4; kl++) {
            uint32_t a0, a1, a2, a3;
            ldsm_x4(a0, a1, a2, a3, hb + r_a * 128 + (((kl * 2 + seg_hi) ^ (r_a & 7)) << 4));
            int r_b = kl * 16 + r_bb;
#pragma unroll
            for (int q2 = 0; q2 < 2; q2++) {
                int ng = nh * 2 + q2;
                uint32_t b0, b1, b2, b3;
                ldsm_x4_t(b0, b1, b2, b3, wb + r_b * 128 + (((ng * 2 + seg_hi) ^ (r_b & 7)) << 4));
                mma_f16(acc[q2 * 2],     a0, a1, a2, a3, b0, b1);
                mma_f16(acc[q2 * 2 + 1], a0, a1, a2, a3, b2, b3);
            }
        }
        if (kt + 1 < KTILES) {
            sts_cvt16(sH[buf ^ 1], srow, q * 2, hr[0], hr[1], hr[2], hr[3]);
            sts_cvt16(sW[buf ^ 1], srow, q * 2, wr[0], wr[1], wr[2], wr[3]);
        }
        __syncthreads();
    }

    // ---- accums -> whl fp16 ----
    {
        int g = lane >> 2, c = lane & 3;
        int rowA = mw * 16 + g, rowB = rowA + 8;
#pragma unroll
        for (int nt = 0; nt < 4; nt++) {
            int col = nh * 32 + nt * 8 + 2 * c;
            *(uint32_t*)&whl[rowA][col] = cvt_f16x2(acc[nt][0], acc[nt][1]);
            *(uint32_t*)&whl[rowB][col] = cvt_f16x2(acc[nt][2], acc[nt][3]);
        }
    }
    __syncthreads();

    // ---- s1/s2 (fp32) + M2 atomicMax ----
    {
        int r = t >> 2, qq = t & 3;
        float x1 = 0.f, x2 = 0.f;
#pragma unroll
        for (int j = 0; j < 8; j++) {
            float2 f = __half22float2(*(__half2*)&whl[r][qq * 16 + 2 * j]);
            x1 += f.x * a_s[qq * 16 + 2 * j] + f.y * a_s[qq * 16 + 2 * j + 1];
            x2 += f.x * a_s[64 + qq * 16 + 2 * j] + f.y * a_s[64 + qq * 16 + 2 * j + 1];
        }
        x1 += __shfl_xor_sync(0xffffffffu, x1, 1);
        x1 += __shfl_xor_sync(0xffffffffu, x1, 2);
        x2 += __shfl_xor_sync(0xffffffffu, x2, 1);
        x2 += __shfl_xor_sync(0xffffffffu, x2, 2);
        if (qq == 0) { g_s1[row0 + r] = x1; g_s2[row0 + r] = x2; }
        float mx = (qq == 0) ? fmaxf(x2, 0.f) : 0.f;
#pragma unroll
        for (int m = 16; m > 0; m >>= 1)
            mx = fmaxf(mx, __shfl_xor_sync(0xffffffffu, mx, m));
        if (lane == 0) atomicMax(&g_M2i, __float_as_int(mx));
    }

    // ---- frag assembly: 4 tiles of 16 rows, 2 uint4 per thread ----
#pragma unroll
    for (int it = 0; it < 2; it++) {
        int tile = (t >> 7) + 2 * it;
        int p = (t >> 5) & 3;
        int l5 = t & 31;
        int gg = l5 >> 2, c4 = l5 & 3;
        int r = tile * 16 + 2 * c4;
        int n0 = 16 * p + gg, n1 = n0 + 8;
        __half2 x = __halves2half2(whl[r][n0],     whl[r + 1][n0]);
        __half2 y = __halves2half2(whl[r + 8][n0], whl[r + 9][n0]);
        __half2 z = __halves2half2(whl[r][n1],     whl[r + 1][n1]);
        __half2 v = __halves2half2(whl[r + 8][n1], whl[r + 9][n1]);
        uint4 o;
        o.x = *(uint32_t*)&x; o.y = *(uint32_t*)&y;
        o.z = *(uint32_t*)&z; o.w = *(uint32_t*)&v;
        g_WhF[(size_t)(blockIdx.x * 4 + tile) * 128 + p * 32 + l5] = o;
    }
}

// ---------------------------------------------------------------------------
// Kernel 2: masked-softmax GEMM, P built in mma A-fragment regs.
// Per-row shift m_i = lrelu(s1_i + M2) guarantees p <= 1 (fp16-safe).
// Row sums via ones-MMA. adj: 4-slot ring, distance-3 prefetch. B: depth-2.
// ---------------------------------------------------------------------------
__global__ __launch_bounds__(256, 2) void gat_attn(const int* __restrict__ adj) {
    __shared__ __align__(16) float s2s[KS];      // s2 * log2(e)

    int t = threadIdx.x;
    int lane = t & 31, warp = t >> 5;
    int g = lane >> 2, c = lane & 3;
    int i0 = blockIdx.x * BM;
    int sp = blockIdx.y;
    size_t jbase = (size_t)sp * KS;

    {
        float4 sv = ((const float4*)(g_s2 + jbase))[t];
        sv.x *= L2E; sv.y *= L2E; sv.z *= L2E; sv.w *= L2E;
        ((float4*)s2s)[t] = sv;
    }
    __syncthreads();

    int r0 = i0 + warp * 16 + g;
    float M2 = __int_as_float(g_M2i);
    float s10 = g_s1[r0], s11 = g_s1[r0 + 8];
    float zz0 = s10 + M2, zz1 = s11 + M2;
    float m0 = fmaxf(zz0, ALPHA * zz0);
    float m1 = fmaxf(zz1, ALPHA * zz1);
    float u0 = (s10 - m0) * L2E, v0 = (ALPHA * s10 - m0) * L2E;
    float u1 = (s11 - m1) * L2E, v1 = (ALPHA * s11 - m1) * L2E;

    const int* adjA = adj + (size_t)r0 * N_NODES + jbase + 2 * c;
    const int* adjB = adjA + (size_t)8 * N_NODES;
    const uint4* whf = g_WhF + (jbase >> 4) * 128 + lane;
    const float* s2p = s2s + 2 * c;

    float acc[8][4];
#pragma unroll
    for (int n = 0; n < 8; n++)
#pragma unroll
        for (int k = 0; k < 4; k++) acc[n][k] = 0.f;
    float accl[4] = {0.f, 0.f, 0.f, 0.f};
    const uint32_t ONE2 = 0x3C003C00u;

    int2 aA1[4], aA2[4], aB1[4], aB2[4];
    uint4 Bf[2][4];
#pragma unroll
    for (int s = 0; s < 3; s++) {
        int off = s * 16;
        aA1[s] = *(const int2*)(adjA + off);
        aA2[s] = *(const int2*)(adjA + off + 8);
        aB1[s] = *(const int2*)(adjB + off);
        aB2[s] = *(const int2*)(adjB + off + 8);
    }
    Bf[0][0] = whf[0]; Bf[0][1] = whf[32]; Bf[0][2] = whf[64]; Bf[0][3] = whf[96];

#pragma unroll 4
    for (int step = 0; step < NSTEP; step++) {
        int cur = step & 1;
        int ci = step & 3;
        if (step + 3 < NSTEP) {
            int off = (step + 3) * 16;
            int ix = (step + 3) & 3;
            aA1[ix] = *(const int2*)(adjA + off);
            aA2[ix] = *(const int2*)(adjA + off + 8);
            aB1[ix] = *(const int2*)(adjB + off);
            aB2[ix] = *(const int2*)(adjB + off + 8);
        }
        if (step + 1 < NSTEP) {
            const uint4* bp = whf + (size_t)(step + 1) * 128;
            Bf[cur ^ 1][0] = bp[0]; Bf[cur ^ 1][1] = bp[32];
            Bf[cur ^ 1][2] = bp[64]; Bf[cur ^ 1][3] = bp[96];
        }

        float2 t1 = *(const float2*)(s2p + step * 16);
        float2 t2 = *(const float2*)(s2p + step * 16 + 8);
        float q1x = ALPHA * t1.x, q1y = ALPHA * t1.y;
        float q2x = ALPHA * t2.x, q2y = ALPHA * t2.y;

        float p00 = (aA1[ci].x > 0) ? ex2f(fmaxf(u0 + t1.x, v0 + q1x)) : 0.f;
        float p01 = (aA1[ci].y > 0) ? ex2f(fmaxf(u0 + t1.y, v0 + q1y)) : 0.f;
        float p02 = (aA2[ci].x > 0) ? ex2f(fmaxf(u0 + t2.x, v0 + q2x)) : 0.f;
        float p03 = (aA2[ci].y > 0) ? ex2f(fmaxf(u0 + t2.y, v0 + q2y)) : 0.f;
        float p10 = (aB1[ci].x > 0) ? ex2f(fmaxf(u1 + t1.x, v1 + q1x)) : 0.f;
        float p11 = (aB1[ci].y > 0) ? ex2f(fmaxf(u1 + t1.y, v1 + q1y)) : 0.f;
        float p12 = (aB2[ci].x > 0) ? ex2f(fmaxf(u1 + t2.x, v1 + q2x)) : 0.f;
        float p13 = (aB2[ci].y > 0) ? ex2f(fmaxf(u1 + t2.y, v1 + q2y)) : 0.f;

        uint32_t a0 = cvt_f16x2(p00, p01);
        uint32_t a1 = cvt_f16x2(p10, p11);
        uint32_t a2 = cvt_f16x2(p02, p03);
        uint32_t a3 = cvt_f16x2(p12, p13);

        mma_f16(acc[0], a0, a1, a2, a3, Bf[cur][0].x, Bf[cur][0].y);
        mma_f16(acc[1], a0, a1, a2, a3, Bf[cur][0].z, Bf[cur][0].w);
        mma_f16(acc[2], a0, a1, a2, a3, Bf[cur][1].x, Bf[cur][1].y);
        mma_f16(acc[3], a0, a1, a2, a3, Bf[cur][1].z, Bf[cur][1].w);
        mma_f16(acc[4], a0, a1, a2, a3, Bf[cur][2].x, Bf[cur][2].y);
        mma_f16(acc[5], a0, a1, a2, a3, Bf[cur][2].z, Bf[cur][2].w);
        mma_f16(acc[6], a0, a1, a2, a3, Bf[cur][3].x, Bf[cur][3].y);
        mma_f16(acc[7], a0, a1, a2, a3, Bf[cur][3].z, Bf[cur][3].w);
        mma_f16(accl,   a0, a1, a2, a3, ONE2, ONE2);
    }

    if (c == 0) {
        g_pl[sp][r0] = accl[0];
        g_pl[sp][r0 + 8] = accl[2];
    }
    float* pb = &g_pacc[sp][0][0];
#pragma unroll
    for (int ng = 0; ng < 8; ng++) {
        *(float2*)(pb + (size_t)r0 * F_OUT + ng * 8 + 2 * c)       = make_float2(acc[ng][0], acc[ng][1]);
        *(float2*)(pb + (size_t)(r0 + 8) * F_OUT + ng * 8 + 2 * c) = make_float2(acc[ng][2], acc[ng][3]);
    }
}

// ---------------------------------------------------------------------------
// Kernel 3: merge splits, normalize, elu.
// ---------------------------------------------------------------------------
__global__ __launch_bounds__(256) void gat_merge(float* __restrict__ out) {
    int idx = blockIdx.x * 256 + threadIdx.x;
    int i = idx >> 6;
    float v = 0.f, l = 0.f;
#pragma unroll
    for (int s = 0; s < SPLITS; s++) {
        v += g_pacc[s][i][idx & 63];
        l += g_pl[s][i];
    }
    float r = v / l;
    out[idx] = r > 0.f ? r : expm1f(r);
}

// ---------------------------------------------------------------------------
extern "C" void kernel_launch(void* const* d_in, const int* in_sizes, int n_in,
                              void* d_out, int out_size) {
    const float* h   = (const float*)d_in[0];
    const float* W   = (const float*)d_in[1];
    const float* a   = (const float*)d_in[2];
    const int*   adj = (const int*)d_in[3];
    float* out = (float*)d_out;

    gat_gemm<<<N_NODES / GROWS, 256>>>(h, W, a);
    gat_attn<<<dim3(N_NODES / BM, SPLITS), 256>>>(adj);
    gat_merge<<<N_NODES * F_OUT / 256, 256>>>(out);
}

// round 15
// speedup vs baseline: 8.5281x; 1.0629x over previous
#include <cuda_runtime.h>
#include <cuda_fp16.h>
#include <cstdint>

#define N_NODES 8192
#define F_IN    512
#define F_OUT   64
#define ALPHA   0.2f
#define BM      128                  // i rows per attn block (8 warps x 16)
#define SPLITS  8
#define KS      (N_NODES / SPLITS)   // 1024
#define NSTEP   (KS / 16)            // 64
#define L2E     1.4426950408889634f
#define GROWS   32                   // rows per gemm block
#define KTILES  (F_IN / 64)          // 8

__device__ __align__(16) uint4  g_WhF[(N_NODES / 16) * 4 * 32];  // B-frag layout (j-permuted), 1MB
__device__ __align__(16) float  g_s1[N_NODES];
__device__ __align__(16) float  g_s2[N_NODES];
__device__ int g_M2i;                // max(0, max s2) as int-reinterp float (atomicMax, idempotent)
__device__ __align__(16) float  g_pacc[SPLITS][N_NODES][F_OUT];
__device__ __align__(16) float  g_pl[SPLITS][N_NODES];

// ---------------- helpers ----------------
__device__ __forceinline__ uint32_t smem_u32(const void* p) {
    uint32_t a;
    asm("{ .reg .u64 t; cvta.to.shared.u64 t, %1; cvt.u32.u64 %0, t; }" : "=r"(a) : "l"(p));
    return a;
}
__device__ __forceinline__ uint32_t cvt_f16x2(float lo, float hi) {
    uint32_t r;
    asm("cvt.rn.f16x2.f32 %0, %1, %2;" : "=r"(r) : "f"(hi), "f"(lo));
    return r;
}
__device__ __forceinline__ float ex2f(float x) {
    float r;
    asm("ex2.approx.ftz.f32 %0, %1;" : "=f"(r) : "f"(x));
    return r;
}
__device__ __forceinline__ void ldsm_x4(uint32_t& r0, uint32_t& r1, uint32_t& r2, uint32_t& r3, uint32_t addr) {
    asm volatile("ldmatrix.sync.aligned.m8n8.x4.shared.b16 {%0,%1,%2,%3}, [%4];"
                 : "=r"(r0), "=r"(r1), "=r"(r2), "=r"(r3) : "r"(addr));
}
__device__ __forceinline__ void ldsm_x4_t(uint32_t& r0, uint32_t& r1, uint32_t& r2, uint32_t& r3, uint32_t addr) {
    asm volatile("ldmatrix.sync.aligned.m8n8.x4.trans.shared.b16 {%0,%1,%2,%3}, [%4];"
                 : "=r"(r0), "=r"(r1), "=r"(r2), "=r"(r3) : "r"(addr));
}
__device__ __forceinline__ void mma_f16(float* c, uint32_t a0, uint32_t a1, uint32_t a2, uint32_t a3,
                                        uint32_t b0, uint32_t b1) {
    asm volatile(
        "mma.sync.aligned.m16n8k16.row.col.f32.f16.f16.f32 "
        "{%0,%1,%2,%3}, {%4,%5,%6,%7}, {%8,%9}, {%0,%1,%2,%3};"
        : "+f"(c[0]), "+f"(c[1]), "+f"(c[2]), "+f"(c[3])
        : "r"(a0), "r"(a1), "r"(a2), "r"(a3), "r"(b0), "r"(b1));
}
__device__ __forceinline__ void sts_cvt16(char* base, int row, int s0,
                                          float4 v0, float4 v1, float4 v2, float4 v3) {
    uint4 o1, o2;
    o1.x = cvt_f16x2(v0.x, v0.y); o1.y = cvt_f16x2(v0.z, v0.w);
    o1.z = cvt_f16x2(v1.x, v1.y); o1.w = cvt_f16x2(v1.z, v1.w);
    o2.x = cvt_f16x2(v2.x, v2.y); o2.y = cvt_f16x2(v2.z, v2.w);
    o2.z = cvt_f16x2(v3.x, v3.y); o2.w = cvt_f16x2(v3.z, v3.w);
    *(uint4*)(base + row * 128 + (((s0    ) ^ (row & 7)) << 4)) = o1;
    *(uint4*)(base + row * 128 + (((s0 + 1) ^ (row & 7)) << 4)) = o2;
}

// ---------------------------------------------------------------------------
// Kernel 1: Wh = h @ W via fp16 mma.sync. 32 rows/block, grid 256.
// Warp tile 16m x 16n (mw = warp&1, nh = warp>>2-bits). Fused epilogue:
// s1/s2 (fp32), M2 atomicMax, j-permuted B-fragment assembly.
// ---------------------------------------------------------------------------
__global__ __launch_bounds__(256) void gat_gemm(const float* __restrict__ h,
                                                const float* __restrict__ W,
                                                const float* __restrict__ a) {
    __shared__ __align__(16) char sH[2][GROWS * 128];   // fp16 [row][k64], swizzled (4KB/buf)
    __shared__ __align__(16) char sW[2][64 * 128];      // fp16 [k64][n64], swizzled (8KB/buf)
    __shared__ __half whl[GROWS][72];
    __shared__ float a_s[128];

    int t = threadIdx.x;
    int lane = t & 31, warp = t >> 5;
    int mw = warp & 1, nh = warp >> 1;       // m-tile 0..1, n-16-group 0..3
    int seg_hi = lane >> 4;
    int row0 = blockIdx.x * GROWS;

    if (t < 128) a_s[t] = a[t];

    // H staging: 32 rows x 8 threads, 8 floats each
    int srowH = t >> 3, qh = t & 7;
    const float4* hsrc = (const float4*)h + (size_t)(row0 + srowH) * 128 + qh * 2;
    // W staging: 64 rows x 4 threads, 16 floats each
    int srowW = t >> 2, qw = t & 3;
    const float4* wsrc = (const float4*)W + (size_t)srowW * 16 + qw * 4;

    float4 hr[2], wr[4];
    hr[0] = hsrc[0]; hr[1] = hsrc[1];
#pragma unroll
    for (int j = 0; j < 4; j++) wr[j] = wsrc[j];
    {
        uint4 o;
        o.x = cvt_f16x2(hr[0].x, hr[0].y); o.y = cvt_f16x2(hr[0].z, hr[0].w);
        o.z = cvt_f16x2(hr[1].x, hr[1].y); o.w = cvt_f16x2(hr[1].z, hr[1].w);
        *(uint4*)(sH[0] + srowH * 128 + ((qh ^ (srowH & 7)) << 4)) = o;
    }
    sts_cvt16(sW[0], srowW, qw * 2, wr[0], wr[1], wr[2], wr[3]);
    __syncthreads();

    float acc[2][4];
#pragma unroll
    for (int n = 0; n < 2; n++)
#pragma unroll
        for (int k = 0; k < 4; k++) acc[n][k] = 0.f;

    int r_a = mw * 16 + (lane & 15);
    int r_bb = lane & 15;

#pragma unroll 1
    for (int kt = 0; kt < KTILES; kt++) {
        int buf = kt & 1;
        if (kt + 1 < KTILES) {
            hr[0] = hsrc[(kt + 1) * 16];             // +64 floats per k-tile
            hr[1] = hsrc[(kt + 1) * 16 + 1];
#pragma unroll
            for (int j = 0; j < 4; j++)
                wr[j] = wsrc[(size_t)(kt + 1) * 1024 + j];  // +64 W rows per k-tile
        }
        uint32_t hb = smem_u32(sH[buf]);
        uint32_t wb = smem_u32(sW[buf]);
#pragma unroll
        for (int kl = 0; kl < 4; kl++) {
            uint32_t a0, a1, a2, a3;
            ldsm_x4(a0, a1, a2, a3, hb + r_a * 128 + (((kl * 2 + seg_hi) ^ (r_a & 7)) << 4));
            int r_b = kl * 16 + r_bb;
            uint32_t b0, b1, b2, b3;
            ldsm_x4_t(b0, b1, b2, b3, wb + r_b * 128 + (((nh * 2 + seg_hi) ^ (r_b & 7)) << 4));
            mma_f16(acc[0], a0, a1, a2, a3, b0, b1);
            mma_f16(acc[1], a0, a1, a2, a3, b2, b3);
        }
        if (kt + 1 < KTILES) {
            uint4 o;
            o.x = cvt_f16x2(hr[0].x, hr[0].y); o.y = cvt_f16x2(hr[0].z, hr[0].w);
            o.z = cvt_f16x2(hr[1].x, hr[1].y); o.w = cvt_f16x2(hr[1].z, hr[1].w);
            *(uint4*)(sH[buf ^ 1] + srowH * 128 + ((qh ^ (srowH & 7)) << 4)) = o;
            sts_cvt16(sW[buf ^ 1], srowW, qw * 2, wr[0], wr[1], wr[2], wr[3]);
        }
        __syncthreads();
    }

    // ---- accums -> whl fp16 ----
    {
        int g = lane >> 2, cc = lane & 3;
        int rowA = mw * 16 + g, rowB = rowA + 8;
#pragma unroll
        for (int nt = 0; nt < 2; nt++) {
            int col = nh * 16 + nt * 8 + 2 * cc;
            *(uint32_t*)&whl[rowA][col] = cvt_f16x2(acc[nt][0], acc[nt][1]);
            *(uint32_t*)&whl[rowB][col] = cvt_f16x2(acc[nt][2], acc[nt][3]);
        }
    }
    __syncthreads();

    // ---- s1/s2 (fp32) + M2 atomicMax: 32 rows x 8 threads ----
    {
        int r = t >> 3, qq = t & 7;
        float x1 = 0.f, x2 = 0.f;
#pragma unroll
        for (int j = 0; j < 4; j++) {
            float2 f = __half22float2(*(__half2*)&whl[r][qq * 8 + 2 * j]);
            x1 += f.x * a_s[qq * 8 + 2 * j] + f.y * a_s[qq * 8 + 2 * j + 1];
            x2 += f.x * a_s[64 + qq * 8 + 2 * j] + f.y * a_s[64 + qq * 8 + 2 * j + 1];
        }
        x1 += __shfl_xor_sync(0xffffffffu, x1, 1);
        x1 += __shfl_xor_sync(0xffffffffu, x1, 2);
        x1 += __shfl_xor_sync(0xffffffffu, x1, 4);
        x2 += __shfl_xor_sync(0xffffffffu, x2, 1);
        x2 += __shfl_xor_sync(0xffffffffu, x2, 2);
        x2 += __shfl_xor_sync(0xffffffffu, x2, 4);
        if (qq == 0) { g_s1[row0 + r] = x1; g_s2[row0 + r] = x2; }
        float mx = (qq == 0) ? fmaxf(x2, 0.f) : 0.f;
#pragma unroll
        for (int m = 16; m > 0; m >>= 1)
            mx = fmaxf(mx, __shfl_xor_sync(0xffffffffu, mx, m));
        if (lane == 0) atomicMax(&g_M2i, __float_as_int(mx));
    }

    // ---- frag assembly (j-PERMUTED): lane c4's b0={j 4c4,4c4+1}, b1={j 4c4+2,4c4+3} ----
    {
        int tile = t >> 7;                // 0..1
        int p = (t >> 5) & 3;
        int l5 = t & 31;
        int c4 = l5 & 3;
        int gg = l5 >> 2;
        int r = tile * 16 + 4 * c4;
        int n0 = 16 * p + gg, n1 = n0 + 8;
        __half2 x = __halves2half2(whl[r][n0],     whl[r + 1][n0]);
        __half2 y = __halves2half2(whl[r + 2][n0], whl[r + 3][n0]);
        __half2 z = __halves2half2(whl[r][n1],     whl[r + 1][n1]);
        __half2 v = __halves2half2(whl[r + 2][n1], whl[r + 3][n1]);
        uint4 o;
        o.x = *(uint32_t*)&x; o.y = *(uint32_t*)&y;
        o.z = *(uint32_t*)&z; o.w = *(uint32_t*)&v;
        g_WhF[(size_t)(blockIdx.x * 2 + tile) * 128 + p * 32 + l5] = o;
    }
}

// ---------------------------------------------------------------------------
// Kernel 2: masked-softmax GEMM, P built in mma A-fragment regs.
// j-permuted contraction: lane c covers j = 4c..4c+3 -> ONE int4 adj load
// per row per step and one LDS.128 for s2. Per-row shift keeps p <= 1.
// Row sums via ones-MMA. adj: 4-slot ring, distance-3 prefetch. B: depth-2.
// ---------------------------------------------------------------------------
__global__ __launch_bounds__(256, 2) void gat_attn(const int* __restrict__ adj) {
    __shared__ __align__(16) float s2s[KS];      // s2 * log2(e)

    int t = threadIdx.x;
    int lane = t & 31, warp = t >> 5;
    int g = lane >> 2, c = lane & 3;
    int i0 = blockIdx.x * BM;
    int sp = blockIdx.y;
    size_t jbase = (size_t)sp * KS;

    {
        float4 sv = ((const float4*)(g_s2 + jbase))[t];
        sv.x *= L2E; sv.y *= L2E; sv.z *= L2E; sv.w *= L2E;
        ((float4*)s2s)[t] = sv;
    }
    __syncthreads();

    int r0 = i0 + warp * 16 + g;
    float M2 = __int_as_float(g_M2i);
    float s10 = g_s1[r0], s11 = g_s1[r0 + 8];
    float zz0 = s10 + M2, zz1 = s11 + M2;
    float m0 = fmaxf(zz0, ALPHA * zz0);
    float m1 = fmaxf(zz1, ALPHA * zz1);
    float u0 = (s10 - m0) * L2E, v0 = (ALPHA * s10 - m0) * L2E;
    float u1 = (s11 - m1) * L2E, v1 = (ALPHA * s11 - m1) * L2E;

    const int* adjA = adj + (size_t)r0 * N_NODES + jbase + 4 * c;
    const int* adjB = adjA + (size_t)8 * N_NODES;
    const uint4* whf = g_WhF + (jbase >> 4) * 128 + lane;
    const float* s2p = s2s + 4 * c;

    float acc[8][4];
#pragma unroll
    for (int n = 0; n < 8; n++)
#pragma unroll
        for (int k = 0; k < 4; k++) acc[n][k] = 0.f;
    float accl[4] = {0.f, 0.f, 0.f, 0.f};
    const uint32_t ONE2 = 0x3C003C00u;

    int4 rA[4], rB[4];
    uint4 Bf[2][4];
#pragma unroll
    for (int s = 0; s < 3; s++) {
        rA[s] = *(const int4*)(adjA + s * 16);
        rB[s] = *(const int4*)(adjB + s * 16);
    }
    Bf[0][0] = whf[0]; Bf[0][1] = whf[32]; Bf[0][2] = whf[64]; Bf[0][3] = whf[96];

#pragma unroll 4
    for (int step = 0; step < NSTEP; step++) {
        int cur = step & 1;
        int ci = step & 3;
        if (step + 3 < NSTEP) {
            int ix = (step + 3) & 3;
            rA[ix] = *(const int4*)(adjA + (step + 3) * 16);
            rB[ix] = *(const int4*)(adjB + (step + 3) * 16);
        }
        if (step + 1 < NSTEP) {
            const uint4* bp = whf + (size_t)(step + 1) * 128;
            Bf[cur ^ 1][0] = bp[0]; Bf[cur ^ 1][1] = bp[32];
            Bf[cur ^ 1][2] = bp[64]; Bf[cur ^ 1][3] = bp[96];
        }

        int4 aA = rA[ci], aB = rB[ci];
        float4 tv = *(const float4*)(s2p + step * 16);
        float qx = ALPHA * tv.x, qy = ALPHA * tv.y;
        float qz = ALPHA * tv.z, qw = ALPHA * tv.w;

        float p00 = (aA.x > 0) ? ex2f(fmaxf(u0 + tv.x, v0 + qx)) : 0.f;
        float p01 = (aA.y > 0) ? ex2f(fmaxf(u0 + tv.y, v0 + qy)) : 0.f;
        float p02 = (aA.z > 0) ? ex2f(fmaxf(u0 + tv.z, v0 + qz)) : 0.f;
        float p03 = (aA.w > 0) ? ex2f(fmaxf(u0 + tv.w, v0 + qw)) : 0.f;
        float p10 = (aB.x > 0) ? ex2f(fmaxf(u1 + tv.x, v1 + qx)) : 0.f;
        float p11 = (aB.y > 0) ? ex2f(fmaxf(u1 + tv.y, v1 + qy)) : 0.f;
        float p12 = (aB.z > 0) ? ex2f(fmaxf(u1 + tv.z, v1 + qz)) : 0.f;
        float p13 = (aB.w > 0) ? ex2f(fmaxf(u1 + tv.w, v1 + qw)) : 0.f;

        uint32_t a0 = cvt_f16x2(p00, p01);   // j 4c,4c+1   (rows A)
        uint32_t a1 = cvt_f16x2(p10, p11);   // j 4c,4c+1   (rows B)
        uint32_t a2 = cvt_f16x2(p02, p03);   // j 4c+2,4c+3 (rows A)
        uint32_t a3 = cvt_f16x2(p12, p13);   // j 4c+2,4c+3 (rows B)

        mma_f16(acc[0], a0, a1, a2, a3, Bf[cur][0].x, Bf[cur][0].y);
        mma_f16(acc[1], a0, a1, a2, a3, Bf[cur][0].z, Bf[cur][0].w);
        mma_f16(acc[2], a0, a1, a2, a3, Bf[cur][1].x, Bf[cur][1].y);
        mma_f16(acc[3], a0, a1, a2, a3, Bf[cur][1].z, Bf[cur][1].w);
        mma_f16(acc[4], a0, a1, a2, a3, Bf[cur][2].x, Bf[cur][2].y);
        mma_f16(acc[5], a0, a1, a2, a3, Bf[cur][2].z, Bf[cur][2].w);
        mma_f16(acc[6], a0, a1, a2, a3, Bf[cur][3].x, Bf[cur][3].y);
        mma_f16(acc[7], a0, a1, a2, a3, Bf[cur][3].z, Bf[cur][3].w);
        mma_f16(accl,   a0, a1, a2, a3, ONE2, ONE2);
    }

    if (c == 0) {
        g_pl[sp][r0] = accl[0];
        g_pl[sp][r0 + 8] = accl[2];
    }
    float* pb = &g_pacc[sp][0][0];
#pragma unroll
    for (int ng = 0; ng < 8; ng++) {
        *(float2*)(pb + (size_t)r0 * F_OUT + ng * 8 + 2 * c)       = make_float2(acc[ng][0], acc[ng][1]);
        *(float2*)(pb + (size_t)(r0 + 8) * F_OUT + ng * 8 + 2 * c) = make_float2(acc[ng][2], acc[ng][3]);
    }
}

// ---------------------------------------------------------------------------
// Kernel 3: merge splits, normalize, elu.
// ---------------------------------------------------------------------------
__global__ __launch_bounds__(256) void gat_merge(float* __restrict__ out) {
    int idx = blockIdx.x * 256 + threadIdx.x;
    int i = idx >> 6;
    float v = 0.f, l = 0.f;
#pragma unroll
    for (int s = 0; s < SPLITS; s++) {
        v += g_pacc[s][i][idx & 63];
        l += g_pl[s][i];
    }
    float r = v / l;
    out[idx] = r > 0.f ? r : expm1f(r);
}

// ---------------------------------------------------------------------------
extern "C" void kernel_launch(void* const* d_in, const int* in_sizes, int n_in,
                              void* d_out, int out_size) {
    const float* h   = (const float*)d_in[0];
    const float* W   = (const float*)d_in[1];
    const float* a   = (const float*)d_in[2];
    const int*   adj = (const int*)d_in[3];
    float* out = (float*)d_out;

    gat_gemm<<<N_NODES / GROWS, 256>>>(h, W, a);
    gat_attn<<<dim3(N_NODES / BM, SPLITS), 256>>>(adj);
    gat_merge<<<N_NODES * F_OUT / 256, 256>>>(out);
}

// round 16
// speedup vs baseline: 9.2114x; 1.0801x over previous
#include <cuda_runtime.h>
#include <cuda_fp16.h>
#include <cstdint>

#define N_NODES 8192
#define F_IN    512
#define F_OUT   64
#define ALPHA   0.2f
#define BM      128                  // i rows per attn tile (8 warps x 16)
#define SPLITS  8
#define KS      (N_NODES / SPLITS)   // 1024
#define NSTEP   (KS / 16)            // 64
#define NTILES  ((N_NODES / BM) * SPLITS)  // 512
#define ATTN_GRID 296
#define L2E     1.4426950408889634f
#define GROWS   32                   // rows per gemm block
#define KTILES  (F_IN / 64)          // 8

__device__ __align__(16) uint4  g_WhF[(N_NODES / 16) * 4 * 32];  // B-frag layout (j-permuted), 1MB
__device__ __align__(16) float  g_s1[N_NODES];
__device__ __align__(16) float  g_s2[N_NODES];
__device__ int g_M2i;                // max(0, max s2) as int-reinterp float (atomicMax, idempotent)
__device__ int g_ticket;             // attn tile ticket counter (reset by gat_gemm each call)
__device__ __align__(16) float  g_pacc[SPLITS][N_NODES][F_OUT];
__device__ __align__(16) float  g_pl[SPLITS][N_NODES];

// ---------------- helpers ----------------
__device__ __forceinline__ uint32_t smem_u32(const void* p) {
    uint32_t a;
    asm("{ .reg .u64 t; cvta.to.shared.u64 t, %1; cvt.u32.u64 %0, t; }" : "=r"(a) : "l"(p));
    return a;
}
__device__ __forceinline__ uint32_t cvt_f16x2(float lo, float hi) {
    uint32_t r;
    asm("cvt.rn.f16x2.f32 %0, %1, %2;" : "=r"(r) : "f"(hi), "f"(lo));
    return r;
}
__device__ __forceinline__ float ex2f(float x) {
    float r;
    asm("ex2.approx.ftz.f32 %0, %1;" : "=f"(r) : "f"(x));
    return r;
}
__device__ __forceinline__ void ldsm_x4(uint32_t& r0, uint32_t& r1, uint32_t& r2, uint32_t& r3, uint32_t addr) {
    asm volatile("ldmatrix.sync.aligned.m8n8.x4.shared.b16 {%0,%1,%2,%3}, [%4];"
                 : "=r"(r0), "=r"(r1), "=r"(r2), "=r"(r3) : "r"(addr));
}
__device__ __forceinline__ void ldsm_x2_t(uint32_t& r0, uint32_t& r1, uint32_t addr) {
    asm volatile("ldmatrix.sync.aligned.m8n8.x2.trans.shared.b16 {%0,%1}, [%2];"
                 : "=r"(r0), "=r"(r1) : "r"(addr));
}
__device__ __forceinline__ void mma_f16(float* c, uint32_t a0, uint32_t a1, uint32_t a2, uint32_t a3,
                                        uint32_t b0, uint32_t b1) {
    asm volatile(
        "mma.sync.aligned.m16n8k16.row.col.f32.f16.f16.f32 "
        "{%0,%1,%2,%3}, {%4,%5,%6,%7}, {%8,%9}, {%0,%1,%2,%3};"
        : "+f"(c[0]), "+f"(c[1]), "+f"(c[2]), "+f"(c[3])
        : "r"(a0), "r"(a1), "r"(a2), "r"(a3), "r"(b0), "r"(b1));
}

// ---------------------------------------------------------------------------
// Kernel 1: Wh = h @ W via fp16 mma.sync. 32 rows/block, 512 threads, grid 256.
// Warp tile m16 x n8 (mw = warp&1, nh = warp>>1) -> 4096 warps chip-wide.
// Fused epilogue: s1/s2 (fp32), M2 atomicMax, j-permuted B-frag assembly.
// Also resets the attn ticket counter.
// ---------------------------------------------------------------------------
__global__ __launch_bounds__(512, 2) void gat_gemm(const float* __restrict__ h,
                                                   const float* __restrict__ W,
                                                   const float* __restrict__ a) {
    __shared__ __align__(16) char sH[2][GROWS * 128];   // fp16 [row][k64], swizzled
    __shared__ __align__(16) char sW[2][64 * 128];      // fp16 [k64][n64], swizzled
    __shared__ __half whl[GROWS][72];
    __shared__ float a_s[128];
    __shared__ float sm_mx[16];

    int t = threadIdx.x;
    int lane = t & 31, warp = t >> 5;     // 16 warps
    int mw = warp & 1, nh = warp >> 1;    // m-tile 0..1, n8-group 0..7
    int seg_hi = lane >> 4;
    int row0 = blockIdx.x * GROWS;

    if (t == 0) g_ticket = 0;             // reset attn tickets (stream-ordered)
    if (t < 128) a_s[t] = a[t];

    // H staging: 32 rows x 16 threads, 1 float4 (4 floats -> 8B fp16) each
    int srowH = t >> 4, qh = t & 15;
    const float4* hsrc = (const float4*)h + (size_t)(row0 + srowH) * 128 + qh;
    // W staging: 64 rows x 8 threads, 2 float4 (8 floats -> 16B fp16) each
    int srowW = t >> 3, qw = t & 7;
    const float4* wsrc = (const float4*)W + (size_t)srowW * 16 + qw * 2;

    float4 hr; float4 wr[2];
    hr = hsrc[0];
    wr[0] = wsrc[0]; wr[1] = wsrc[1];
    {
        uint2 o = make_uint2(cvt_f16x2(hr.x, hr.y), cvt_f16x2(hr.z, hr.w));
        *(uint2*)(sH[0] + srowH * 128 + (((qh >> 1) ^ (srowH & 7)) << 4) + (qh & 1) * 8) = o;
        uint4 w16;
        w16.x = cvt_f16x2(wr[0].x, wr[0].y); w16.y = cvt_f16x2(wr[0].z, wr[0].w);
        w16.z = cvt_f16x2(wr[1].x, wr[1].y); w16.w = cvt_f16x2(wr[1].z, wr[1].w);
        *(uint4*)(sW[0] + srowW * 128 + ((qw ^ (srowW & 7)) << 4)) = w16;
    }
    __syncthreads();

    float acc[4] = {0.f, 0.f, 0.f, 0.f};
    int r_a = mw * 16 + (lane & 15);
    int r_bb = lane & 15;

#pragma unroll 1
    for (int kt = 0; kt < KTILES; kt++) {
        int buf = kt & 1;
        if (kt + 1 < KTILES) {
            hr = hsrc[(kt + 1) * 16];                     // +64 floats per k-tile
            wr[0] = wsrc[(size_t)(kt + 1) * 1024];        // +64 W rows per k-tile
            wr[1] = wsrc[(size_t)(kt + 1) * 1024 + 1];
        }
        uint32_t hb = smem_u32(sH[buf]);
        uint32_t wb = smem_u32(sW[buf]);
#pragma unroll
        for (int kl = 0; kl < 4; kl++) {
            uint32_t a0, a1, a2, a3;
            ldsm_x4(a0, a1, a2, a3, hb + r_a * 128 + (((kl * 2 + seg_hi) ^ (r_a & 7)) << 4));
            int r_b = kl * 16 + r_bb;
            uint32_t b0, b1;
            ldsm_x2_t(b0, b1, wb + r_b * 128 + ((nh ^ (r_b & 7)) << 4));
            mma_f16(acc, a0, a1, a2, a3, b0, b1);
        }
        __syncthreads();
        if (kt + 1 < KTILES) {
            uint2 o = make_uint2(cvt_f16x2(hr.x, hr.y), cvt_f16x2(hr.z, hr.w));
            *(uint2*)(sH[buf ^ 1] + srowH * 128 + (((qh >> 1) ^ (srowH & 7)) << 4) + (qh & 1) * 8) = o;
            uint4 w16;
            w16.x = cvt_f16x2(wr[0].x, wr[0].y); w16.y = cvt_f16x2(wr[0].z, wr[0].w);
            w16.z = cvt_f16x2(wr[1].x, wr[1].y); w16.w = cvt_f16x2(wr[1].z, wr[1].w);
            *(uint4*)(sW[buf ^ 1] + srowW * 128 + ((qw ^ (srowW & 7)) << 4)) = w16;
            __syncthreads();
        }
    }

    // ---- accums -> whl fp16 ----
    {
        int g = lane >> 2, cc = lane & 3;
        int rowA = mw * 16 + g, rowB = rowA + 8;
        int col = nh * 8 + 2 * cc;
        *(uint32_t*)&whl[rowA][col] = cvt_f16x2(acc[0], acc[1]);
        *(uint32_t*)&whl[rowB][col] = cvt_f16x2(acc[2], acc[3]);
    }
    __syncthreads();

    // ---- s1/s2 (fp32): 32 rows x 16 threads (4 cols each) + M2 ----
    {
        int r = t >> 4, qq = t & 15;
        float x1 = 0.f, x2 = 0.f;
#pragma unroll
        for (int j = 0; j < 2; j++) {
            float2 f = __half22float2(*(__half2*)&whl[r][qq * 4 + 2 * j]);
            x1 += f.x * a_s[qq * 4 + 2 * j] + f.y * a_s[qq * 4 + 2 * j + 1];
            x2 += f.x * a_s[64 + qq * 4 + 2 * j] + f.y * a_s[64 + qq * 4 + 2 * j + 1];
        }
        x1 += __shfl_xor_sync(0xffffffffu, x1, 1);
        x1 += __shfl_xor_sync(0xffffffffu, x1, 2);
        x1 += __shfl_xor_sync(0xffffffffu, x1, 4);
        x1 += __shfl_xor_sync(0xffffffffu, x1, 8);
        x2 += __shfl_xor_sync(0xffffffffu, x2, 1);
        x2 += __shfl_xor_sync(0xffffffffu, x2, 2);
        x2 += __shfl_xor_sync(0xffffffffu, x2, 4);
        x2 += __shfl_xor_sync(0xffffffffu, x2, 8);
        if (qq == 0) { g_s1[row0 + r] = x1; g_s2[row0 + r] = x2; }
        float mx = (qq == 0) ? fmaxf(x2, 0.f) : 0.f;
#pragma unroll
        for (int m = 16; m > 0; m >>= 1)
            mx = fmaxf(mx, __shfl_xor_sync(0xffffffffu, mx, m));
        if (lane == 0) sm_mx[warp] = mx;
    }
    __syncthreads();
    if (t == 0) {
        float m = sm_mx[0];
#pragma unroll
        for (int i = 1; i < 16; i++) m = fmaxf(m, sm_mx[i]);
        atomicMax(&g_M2i, __float_as_int(m));
    }

    // ---- frag assembly (j-PERMUTED): first 256 threads, 1 uint4 each ----
    if (t < 256) {
        int tile = t >> 7;                // 0..1
        int p = (t >> 5) & 3;
        int l5 = t & 31;
        int c4 = l5 & 3;
        int gg = l5 >> 2;
        int r = tile * 16 + 4 * c4;
        int n0 = 16 * p + gg, n1 = n0 + 8;
        __half2 x = __halves2half2(whl[r][n0],     whl[r + 1][n0]);
        __half2 y = __halves2half2(whl[r + 2][n0], whl[r + 3][n0]);
        __half2 z = __halves2half2(whl[r][n1],     whl[r + 1][n1]);
        __half2 v = __halves2half2(whl[r + 2][n1], whl[r + 3][n1]);
        uint4 o;
        o.x = *(uint32_t*)&x; o.y = *(uint32_t*)&y;
        o.z = *(uint32_t*)&z; o.w = *(uint32_t*)&v;
        g_WhF[(size_t)(blockIdx.x * 2 + tile) * 128 + p * 32 + l5] = o;
    }
}

// ---------------------------------------------------------------------------
// Kernel 2: persistent ticket-scheduled masked-softmax GEMM.
// grid = 296 blocks (2/SM); each pulls tile tickets (sp-major for L2 reuse of
// g_WhF). Per tile identical math to R15 (j-permuted A frags, ones-MMA sums).
// ---------------------------------------------------------------------------
__global__ __launch_bounds__(256, 2) void gat_attn(const int* __restrict__ adj) {
    __shared__ __align__(16) float s2s[KS];      // s2 * log2(e)
    __shared__ int s_tile;

    int t = threadIdx.x;
    int lane = t & 31, warp = t >> 5;
    int g = lane >> 2, c = lane & 3;
    const uint32_t ONE2 = 0x3C003C00u;
    float M2 = __int_as_float(g_M2i);

    for (;;) {
        if (t == 0) s_tile = atomicAdd(&g_ticket, 1);
        __syncthreads();
        int tile = s_tile;
        if (tile >= NTILES) return;
        int sp = tile >> 6;              // 0..7  (64 consecutive tickets share sp)
        int i0 = (tile & 63) * BM;
        size_t jbase = (size_t)sp * KS;

        {
            float4 sv = ((const float4*)(g_s2 + jbase))[t];
            sv.x *= L2E; sv.y *= L2E; sv.z *= L2E; sv.w *= L2E;
            ((float4*)s2s)[t] = sv;
        }
        __syncthreads();

        int r0 = i0 + warp * 16 + g;
        float s10 = g_s1[r0], s11 = g_s1[r0 + 8];
        float zz0 = s10 + M2, zz1 = s11 + M2;
        float m0 = fmaxf(zz0, ALPHA * zz0);
        float m1 = fmaxf(zz1, ALPHA * zz1);
        float u0 = (s10 - m0) * L2E, v0 = (ALPHA * s10 - m0) * L2E;
        float u1 = (s11 - m1) * L2E, v1 = (ALPHA * s11 - m1) * L2E;

        const int* adjA = adj + (size_t)r0 * N_NODES + jbase + 4 * c;
        const int* adjB = adjA + (size_t)8 * N_NODES;
        const uint4* whf = g_WhF + (jbase >> 4) * 128 + lane;
        const float* s2p = s2s + 4 * c;

        float acc[8][4];
#pragma unroll
        for (int n = 0; n < 8; n++)
#pragma unroll
            for (int k = 0; k < 4; k++) acc[n][k] = 0.f;
        float accl[4] = {0.f, 0.f, 0.f, 0.f};

        int4 rA[4], rB[4];
        uint4 Bf[2][4];
#pragma unroll
        for (int s = 0; s < 3; s++) {
            rA[s] = *(const int4*)(adjA + s * 16);
            rB[s] = *(const int4*)(adjB + s * 16);
        }
        Bf[0][0] = whf[0]; Bf[0][1] = whf[32]; Bf[0][2] = whf[64]; Bf[0][3] = whf[96];

#pragma unroll 4
        for (int step = 0; step < NSTEP; step++) {
            int cur = step & 1;
            int ci = step & 3;
            if (step + 3 < NSTEP) {
                int ix = (step + 3) & 3;
                rA[ix] = *(const int4*)(adjA + (step + 3) * 16);
                rB[ix] = *(const int4*)(adjB + (step + 3) * 16);
            }
            if (step + 1 < NSTEP) {
                const uint4* bp = whf + (size_t)(step + 1) * 128;
                Bf[cur ^ 1][0] = bp[0]; Bf[cur ^ 1][1] = bp[32];
                Bf[cur ^ 1][2] = bp[64]; Bf[cur ^ 1][3] = bp[96];
            }

            int4 aA = rA[ci], aB = rB[ci];
            float4 tv = *(const float4*)(s2p + step * 16);
            float qx = ALPHA * tv.x, qy = ALPHA * tv.y;
            float qz = ALPHA * tv.z, qw = ALPHA * tv.w;

            float p00 = (aA.x > 0) ? ex2f(fmaxf(u0 + tv.x, v0 + qx)) : 0.f;
            float p01 = (aA.y > 0) ? ex2f(fmaxf(u0 + tv.y, v0 + qy)) : 0.f;
            float p02 = (aA.z > 0) ? ex2f(fmaxf(u0 + tv.z, v0 + qz)) : 0.f;
            float p03 = (aA.w > 0) ? ex2f(fmaxf(u0 + tv.w, v0 + qw)) : 0.f;
            float p10 = (aB.x > 0) ? ex2f(fmaxf(u1 + tv.x, v1 + qx)) : 0.f;
            float p11 = (aB.y > 0) ? ex2f(fmaxf(u1 + tv.y, v1 + qy)) : 0.f;
            float p12 = (aB.z > 0) ? ex2f(fmaxf(u1 + tv.z, v1 + qz)) : 0.f;
            float p13 = (aB.w > 0) ? ex2f(fmaxf(u1 + tv.w, v1 + qw)) : 0.f;

            uint32_t a0 = cvt_f16x2(p00, p01);
            uint32_t a1 = cvt_f16x2(p10, p11);
            uint32_t a2 = cvt_f16x2(p02, p03);
            uint32_t a3 = cvt_f16x2(p12, p13);

            mma_f16(acc[0], a0, a1, a2, a3, Bf[cur][0].x, Bf[cur][0].y);
            mma_f16(acc[1], a0, a1, a2, a3, Bf[cur][0].z, Bf[cur][0].w);
            mma_f16(acc[2], a0, a1, a2, a3, Bf[cur][1].x, Bf[cur][1].y);
            mma_f16(acc[3], a0, a1, a2, a3, Bf[cur][1].z, Bf[cur][1].w);
            mma_f16(acc[4], a0, a1, a2, a3, Bf[cur][2].x, Bf[cur][2].y);
            mma_f16(acc[5], a0, a1, a2, a3, Bf[cur][2].z, Bf[cur][2].w);
            mma_f16(acc[6], a0, a1, a2, a3, Bf[cur][3].x, Bf[cur][3].y);
            mma_f16(acc[7], a0, a1, a2, a3, Bf[cur][3].z, Bf[cur][3].w);
            mma_f16(accl,   a0, a1, a2, a3, ONE2, ONE2);
        }

        if (c == 0) {
            g_pl[sp][r0] = accl[0];
            g_pl[sp][r0 + 8] = accl[2];
        }
        float* pb = &g_pacc[sp][0][0];
#pragma unroll
        for (int ng = 0; ng < 8; ng++) {
            *(float2*)(pb + (size_t)r0 * F_OUT + ng * 8 + 2 * c)       = make_float2(acc[ng][0], acc[ng][1]);
            *(float2*)(pb + (size_t)(r0 + 8) * F_OUT + ng * 8 + 2 * c) = make_float2(acc[ng][2], acc[ng][3]);
        }
        __syncthreads();   // s2s / s_tile safe for next tile
    }
}

// ---------------------------------------------------------------------------
// Kernel 3: merge splits, normalize, elu (float4 per thread).
// ---------------------------------------------------------------------------
__global__ __launch_bounds__(256) void gat_merge(float* __restrict__ out) {
    int idx4 = blockIdx.x * 256 + threadIdx.x;   // float4 index
    int i = idx4 >> 4;
    int c4 = (idx4 & 15) << 2;
    float4 v = make_float4(0.f, 0.f, 0.f, 0.f);
    float l = 0.f;
#pragma unroll
    for (int s = 0; s < SPLITS; s++) {
        float4 p = *(const float4*)&g_pacc[s][i][c4];
        v.x += p.x; v.y += p.y; v.z += p.z; v.w += p.w;
        l += g_pl[s][i];
    }
    float inv = 1.f / l;
    float4 r;
    r.x = v.x * inv; r.y = v.y * inv; r.z = v.z * inv; r.w = v.w * inv;
    r.x = r.x > 0.f ? r.x : expm1f(r.x);
    r.y = r.y > 0.f ? r.y : expm1f(r.y);
    r.z = r.z > 0.f ? r.z : expm1f(r.z);
    r.w = r.w > 0.f ? r.w : expm1f(r.w);
    *(float4*)(out + (size_t)i * F_OUT + c4) = r;
}

// ---------------------------------------------------------------------------
extern "C" void kernel_launch(void* const* d_in, const int* in_sizes, int n_in,
                              void* d_out, int out_size) {
    const float* h   = (const float*)d_in[0];
    const float* W   = (const float*)d_in[1];
    const float* a   = (const float*)d_in[2];
    const int*   adj = (const int*)d_in[3];
    float* out = (float*)d_out;

    gat_gemm<<<N_NODES / GROWS, 512>>>(h, W, a);
    gat_attn<<<ATTN_GRID, 256>>>(adj);
    gat_merge<<<N_NODES * F_OUT / 4 / 256, 256>>>(out);
}